// round 14
// baseline (speedup 1.0000x reference)
#include <cuda_runtime.h>
#include <cuda_fp16.h>
#include <cstdint>

#define BB 2
#define TT 2048
#define CC 768
#define HH 12
#define DD 64
#define BT (BB*TT)          // 4096 rows
#define C4 (4*CC)           // 3072
#define SCALE_L2E (0.03608439182435161f * 1.4426950408889634f)  // 1/sqrt(C)*log2(e)

// ===================== PTX helpers (sm_80-compatible only) ==================
__device__ __forceinline__ uint32_t smem_u32(const void* p) {
    uint32_t a;
    asm("{ .reg .u64 t; cvta.to.shared.u64 t, %1; cvt.u32.u64 %0, t; }"
        : "=r"(a) : "l"(p));
    return a;
}

#define CP16(s, g) \
    asm volatile("cp.async.cg.shared.global [%0], [%1], 16;" :: "r"(s), "l"(g))
#define CP_COMMIT() asm volatile("cp.async.commit_group;" ::: "memory")
#define CP_WAIT(n)  asm volatile("cp.async.wait_group %0;" :: "n"(n) : "memory")

#define LDSM_X4(r0, r1, r2, r3, a) \
    asm volatile("ldmatrix.sync.aligned.m8n8.x4.shared.b16 {%0,%1,%2,%3}, [%4];" \
        : "=r"(r0), "=r"(r1), "=r"(r2), "=r"(r3) : "r"(a))

#define LDSM_X4T(r0, r1, r2, r3, a) \
    asm volatile("ldmatrix.sync.aligned.m8n8.x4.trans.shared.b16 {%0,%1,%2,%3}, [%4];" \
        : "=r"(r0), "=r"(r1), "=r"(r2), "=r"(r3) : "r"(a))

#define MMA_F16(d, a, b0, b1) \
    asm volatile("mma.sync.aligned.m16n8k16.row.col.f32.f16.f16.f32 " \
        "{%0,%1,%2,%3}, {%4,%5,%6,%7}, {%8,%9}, {%0,%1,%2,%3};" \
        : "+f"((d)[0]), "+f"((d)[1]), "+f"((d)[2]), "+f"((d)[3]) \
        : "r"((a)[0]), "r"((a)[1]), "r"((a)[2]), "r"((a)[3]), "r"(b0), "r"(b1))

#define SWZ(x) ((x) ^ (((x) >> 3) & 0x70))

__device__ __forceinline__ uint32_t pack_h2(float lo, float hi) {
    uint32_t r;
    asm("cvt.rn.f16x2.f32 %0, %1, %2;" : "=r"(r) : "f"(hi), "f"(lo));
    return r;
}
__device__ __forceinline__ uint32_t hexp2_2(uint32_t a) {
    uint32_t r;
    asm("ex2.approx.f16x2 %0, %1;" : "=r"(r) : "r"(a));
    return r;
}
__device__ __forceinline__ float fexp2(float x) {
    float r;
    asm("ex2.approx.ftz.f32 %0, %1;" : "=f"(r) : "f"(x));
    return r;
}

// ===================== scratch (static device memory) ======================
__device__ float g_att[BT*CC];
__device__ float g_x1 [BT*CC];
__device__ __half g_hh [BT*CC];
__device__ __half g_h2h[BT*CC];
__device__ __half g_hidh[(size_t)BT*C4];
// qkv, layout [B,H,T,D], fp16; Q pre-scaled by SCALE_L2E (log2 domain)
__device__ __half g_qh[BT*CC];
__device__ __half g_kh[BT*CC];
__device__ __half g_vh[BT*CC];
__device__ __half g_wqh[HH*DD*CC];
__device__ __half g_wkh[HH*DD*CC];
__device__ __half g_wvh[HH*DD*CC];
__device__ __half g_whh[(size_t)C4*CC];
__device__ __half g_wph[(size_t)CC*C4];

struct QKVOut {
    const __half *w0, *w1, *w2;
    __half *qh, *kh, *vh;
};

// ===================== fused weight prep (ALL weights, ONE launch) =========
__global__ __launch_bounds__(256) void wprep_kernel(
    const float* __restrict__ wq, const float* __restrict__ wk,
    const float* __restrict__ wv, const float* __restrict__ wh,
    const float* __restrict__ wp,
    __half* __restrict__ wqh, __half* __restrict__ wkh,
    __half* __restrict__ wvh, __half* __restrict__ whh,
    __half* __restrict__ wph)
{
    int id = blockIdx.x;
    const float* in; __half* oh;
    int R, Cn, x, y; long zo = 0;
    if (id < 1728) {                 // wq/wk/wv: 3 sections x 12 heads x (2x24)
        int sec = id / 576, r = id % 576;
        int z = r / 48, rr = r % 48;
        x = rr & 1; y = rr >> 1;
        R = CC; Cn = DD;
        zo = (long)z * CC * DD;
        in = (sec == 0) ? wq : (sec == 1) ? wk : wv;
        oh = (sec == 0) ? wqh : (sec == 1) ? wkh : wvh;
    } else if (id < 4032) {          // wh: 96 x-tiles, 24 y-tiles
        int r = id - 1728;
        x = r % 96; y = r / 96;
        R = CC; Cn = C4; in = wh; oh = whh;
    } else {                         // wp: 24 x-tiles, 96 y-tiles
        int r = id - 4032;
        x = r % 24; y = r / 24;
        R = C4; Cn = CC; in = wp; oh = wph;
    }

    __shared__ float ts[32][33];
    int r0 = y * 32, c0 = x * 32;
    int tx = threadIdx.x & 31, ty = threadIdx.x >> 5;
    #pragma unroll
    for (int i = 0; i < 4; i++) {
        int r = r0 + ty + i*8;
        ts[ty + i*8][tx] = in[zo + (size_t)r*Cn + c0 + tx];
    }
    __syncthreads();
    #pragma unroll
    for (int i = 0; i < 4; i++) {
        int cc = ty + i*8;
        size_t oi = zo + (size_t)(c0 + cc)*R + r0 + tx;
        oh[oi] = __float2half(ts[tx][cc]);
    }
}

// ===================== LayerNorm -> fp16 (+opt residual) ===================
template<bool ADD>
__global__ __launch_bounds__(256) void ln_kernel(
    const float* __restrict__ x, const float* __restrict__ add,
    const float* __restrict__ g, const float* __restrict__ be,
    __half* __restrict__ oh, float* __restrict__ outsum)
{
    int row = blockIdx.x;
    int tid = threadIdx.x;
    const float* xr = x + (size_t)row*CC;
    const float* ar = add + (size_t)row*CC;
    float v[3]; float s = 0.f, sq = 0.f;
    #pragma unroll
    for (int i = 0; i < 3; i++) {
        int c = tid + i*256;
        float val = xr[c];
        if (ADD) val += ar[c];
        v[i] = val; s += val; sq = fmaf(val, val, sq);
    }
    #pragma unroll
    for (int o = 16; o > 0; o >>= 1) {
        s  += __shfl_down_sync(0xffffffffu, s,  o);
        sq += __shfl_down_sync(0xffffffffu, sq, o);
    }
    __shared__ float rs[8], rq[8], stat[2];
    if ((tid & 31) == 0) { rs[tid>>5] = s; rq[tid>>5] = sq; }
    __syncthreads();
    if (tid == 0) {
        float ts = 0.f, tq = 0.f;
        #pragma unroll
        for (int i = 0; i < 8; i++) { ts += rs[i]; tq += rq[i]; }
        float mu  = ts * (1.0f/CC);
        float var = tq * (1.0f/CC) - mu*mu;
        stat[0] = mu; stat[1] = rsqrtf(var + 1e-5f);
    }
    __syncthreads();
    float mu = stat[0], rstd = stat[1];
    #pragma unroll
    for (int i = 0; i < 3; i++) {
        int c = tid + i*256;
        float val = (v[i]-mu)*rstd*g[c] + be[c];
        oh[(size_t)row*CC + c] = __float2half(val);
        if (ADD) outsum[(size_t)row*CC + c] = v[i];
    }
}

// ===================== HMMA (mma.sync) GEMM =================================
// C[M,N] = A[M,K] * B[N,K]^T, fp16 1-term.
// MODE 1: +bias, ReLU, store fp16.  MODE 2: +bias +residual, f32 store.
// MODE 3: fused QKV (z = proj*HH + h), out fp16 [B,H,T,D], Q pre-scaled.
template<int NT, int MODE>
__global__ __launch_bounds__(256)
void mm_kernel(
    const __half* __restrict__ Ah, int lda, long strideA,
    const __half* __restrict__ Bh, long strideB,
    float* __restrict__ C, int ldc, long strideC,
    int Ktot,
    const float* __restrict__ bias, const float* __restrict__ res,
    __half* __restrict__ Oh, int ldo,
    QKVOut qkv)
{
    static_assert(NT == 64 || NT == 128, "NT");
    constexpr int SA_H = 0;
    constexpr int SB_H = 16384;
    constexpr int STAGE = 16384 + NT*128;
    constexpr int NB = NT/32;
    constexpr int NW = NT/2;
    constexpr int NT8 = NW/8;
    constexpr int NT16 = NW/16;

    extern __shared__ char smraw[];
    char* sm = (char*)(((uintptr_t)smraw + 1023) & ~(uintptr_t)1023);
    uint32_t sm32 = smem_u32(sm);

    int tid = threadIdx.x;
    int wid = tid >> 5, lane = tid & 31;
    int z = blockIdx.z;
    int proj = 0, hsel = 0;
    if (MODE == 3) {
        proj = z / HH; hsel = z % HH;
        const __half* w = (proj == 0) ? qkv.w0 : (proj == 1) ? qkv.w1 : qkv.w2;
        Bh = w + (size_t)hsel*CC*DD;
    } else {
        Ah += (size_t)z * strideA;
        Bh += (size_t)z * strideB;
        if (MODE == 2) C += (size_t)z * strideC;
    }
    int bm = blockIdx.y * 128, bn = blockIdx.x * NT;

    int wm = (wid & 3) * 32;
    int wn = (wid >> 2) * NW;

    int lr = lane & 7;
    int a_r = lr + ((lane & 8) ? 8 : 0);
    int a_k = (lane & 16) ? 16 : 0;
    int b_r = lr + ((lane & 16) ? 8 : 0);
    int b_k = (lane & 8) ? 16 : 0;

    int g_row = tid >> 3, g_ch = tid & 7;

    float acc[2][NT8][4];
    #pragma unroll
    for (int mt = 0; mt < 2; mt++)
        #pragma unroll
        for (int nt = 0; nt < NT8; nt++)
            #pragma unroll
            for (int j = 0; j < 4; j++) acc[mt][nt][j] = 0.f;

    int nk = Ktot >> 6;

    auto load_stage = [&](int t) {
        int stg = (t & 1) * STAGE;
        int k0 = t << 6;
        #pragma unroll
        for (int i = 0; i < 4; i++) {
            int row = g_row + i*32;
            uint32_t so = sm32 + stg + SWZ(row*128 + g_ch*16);
            CP16(so + SA_H, Ah + (size_t)(bm+row)*lda + k0 + g_ch*8);
        }
        #pragma unroll
        for (int i = 0; i < NB; i++) {
            int row = g_row + i*32;
            uint32_t so = sm32 + stg + SWZ(row*128 + g_ch*16);
            CP16(so + SB_H, Bh + (size_t)(bn+row)*lda + k0 + g_ch*8);
        }
        CP_COMMIT();
    };

    load_stage(0);
    if (nk > 1) load_stage(1);

    for (int t = 0; t < nk; t++) {
        if (t < nk - 1) { CP_WAIT(1); } else { CP_WAIT(0); }
        __syncthreads();
        int stg = (t & 1) * STAGE;
        uint32_t baseA_h = sm32 + stg + SA_H;
        uint32_t baseB_h = sm32 + stg + SB_H;

        #pragma unroll
        for (int kt = 0; kt < 4; kt++) {
            int kb = kt*32;
            uint32_t ah[2][4];
            #pragma unroll
            for (int mt = 0; mt < 2; mt++) {
                uint32_t off = SWZ((wm + mt*16 + a_r)*128 + kb + a_k);
                LDSM_X4(ah[mt][0], ah[mt][1], ah[mt][2], ah[mt][3], baseA_h + off);
            }
            uint32_t bh[NT16][4];
            #pragma unroll
            for (int n2 = 0; n2 < NT16; n2++) {
                uint32_t off = SWZ((wn + n2*16 + b_r)*128 + kb + b_k);
                LDSM_X4(bh[n2][0], bh[n2][1], bh[n2][2], bh[n2][3], baseB_h + off);
            }
            #pragma unroll
            for (int mt = 0; mt < 2; mt++) {
                #pragma unroll
                for (int n2 = 0; n2 < NT16; n2++) {
                    MMA_F16(acc[mt][n2*2],   ah[mt], bh[n2][0], bh[n2][1]);
                    MMA_F16(acc[mt][n2*2+1], ah[mt], bh[n2][2], bh[n2][3]);
                }
            }
        }
        __syncthreads();
        if (t + 2 < nk) load_stage(t + 2);
    }

    // ---- epilogue ----
    int mrow0 = bm + wm + (lane >> 2);
    int ncol0 = bn + wn + (lane & 3) * 2;
    #pragma unroll
    for (int mt = 0; mt < 2; mt++) {
        #pragma unroll
        for (int half = 0; half < 2; half++) {
            int m = mrow0 + mt*16 + half*8;
            #pragma unroll
            for (int nt = 0; nt < NT8; nt++) {
                int n = ncol0 + nt*8;
                float v0 = acc[mt][nt][half*2];
                float v1 = acc[mt][nt][half*2+1];
                if (MODE == 1) {
                    v0 = fmaxf(v0 + bias[n],   0.f);
                    v1 = fmaxf(v1 + bias[n+1], 0.f);
                    __half2 hh2;
                    hh2.x = __float2half(v0); hh2.y = __float2half(v1);
                    *(__half2*)(Oh + (size_t)m*ldo + n) = hh2;
                } else if (MODE == 2) {
                    float2 rr = *(const float2*)(res + (size_t)m*ldc + n);
                    float2 o;
                    o.x = v0 + bias[n]   + rr.x;
                    o.y = v1 + bias[n+1] + rr.y;
                    *(float2*)(C + (size_t)m*ldc + n) = o;
                } else if (MODE == 3) {
                    if (proj == 0) { v0 *= SCALE_L2E; v1 *= SCALE_L2E; }
                    __half2 hh2;
                    hh2.x = __float2half(v0); hh2.y = __float2half(v1);
                    __half* p = (proj == 0) ? qkv.qh : (proj == 1) ? qkv.kh : qkv.vh;
                    size_t o = (((size_t)(m >> 11)*HH + hsel)*TT + (m & (TT-1)))*DD + n;
                    *(__half2*)(p + o) = hh2;
                }
            }
        }
    }
}

// ===================== HMMA flash attention (causal) ========================
// ROUND-11 PROVEN SHAPE: 128 threads (4 warps), CTA owns 64 q rows, warp 16.
// Q fragments register-resident for the whole kernel (latency-critical).
// fp16 1-term; Q pre-scaled by SCALE_L2E (log2 domain); f16x2 ex2;
// P = fp16 A-frags directly; row sums via all-ones B-frag MMA.
__global__ __launch_bounds__(128) void attn_kernel(
    const __half* __restrict__ Qh, const __half* __restrict__ Kh,
    const __half* __restrict__ Vh, float* __restrict__ O)
{
    extern __shared__ char smraw[];
    char* sm = (char*)(((uintptr_t)smraw + 1023) & ~(uintptr_t)1023);
    uint32_t sm32 = smem_u32(sm);

    constexpr int QH_O = 0, STG_O = 8192, STG_SZ = 16384;
    constexpr uint32_t ONE2 = 0x3C003C00u;   // half2(1.0, 1.0)

    int qt = gridDim.x - 1 - (int)blockIdx.x;   // longest first
    int bh = blockIdx.y;
    int b = bh / HH, h = bh % HH;
    int tid = threadIdx.x, wid = tid >> 5, lane = tid & 31;
    size_t base = (size_t)bh * TT * DD;

    // ---- Q tile: 64 rows x 128B = 512 chunks = 128 thr x 4 iters ----
    #pragma unroll
    for (int i = 0; i < 4; i++) {
        int idx = tid + i*128; int row = idx >> 3, ch = idx & 7;
        uint32_t so = sm32 + SWZ(row*128 + ch*16);
        size_t ga = base + (size_t)(qt*64 + row)*DD + ch*8;
        CP16(so + QH_O, Qh + ga);
    }
    auto load_kv = [&](int kt) {
        int stg = STG_O + (kt & 1) * STG_SZ;
        #pragma unroll
        for (int i = 0; i < 4; i++) {
            int idx = tid + i*128; int row = idx >> 3, ch = idx & 7;
            uint32_t so = sm32 + stg + SWZ(row*128 + ch*16);
            size_t ga = base + (size_t)(kt*64 + row)*DD + ch*8;
            CP16(so,        Kh + ga);
            CP16(so + 8192, Vh + ga);
        }
        CP_COMMIT();
    };
    load_kv(0);
    if (qt >= 1) load_kv(1);

    int lr = lane & 7;
    int a_r = lr + ((lane & 8) ? 8 : 0);
    int a_k = (lane & 16) ? 16 : 0;
    int b_r = lr + ((lane & 16) ? 8 : 0);
    int b_k = (lane & 8) ? 16 : 0;
    int v_r = lr + ((lane & 8) ? 8 : 0);
    int v_k = (lane & 16) ? 16 : 0;
    int wm = wid * 16;

    float o[8][4];
    #pragma unroll
    for (int nf = 0; nf < 8; nf++)
        #pragma unroll
        for (int j = 0; j < 4; j++) o[nf][j] = 0.f;
    float osum[4] = {0.f, 0.f, 0.f, 0.f};
    float mrow0 = -1e30f, mrow1 = -1e30f;

    if (qt >= 1) { CP_WAIT(1); } else { CP_WAIT(0); }
    __syncthreads();

    uint32_t qhf[4][4];
    #pragma unroll
    for (int kc = 0; kc < 4; kc++) {
        uint32_t off = SWZ((wm + a_r)*128 + kc*32 + a_k);
        LDSM_X4(qhf[kc][0], qhf[kc][1], qhf[kc][2], qhf[kc][3], sm32 + QH_O + off);
    }

    for (int kt = 0; kt <= qt; kt++) {
        if (kt > 0) {
            if (kt < qt) { CP_WAIT(1); } else { CP_WAIT(0); }
            __syncthreads();
        }
        uint32_t kbh = sm32 + STG_O + (kt & 1)*STG_SZ;
        uint32_t vbh = kbh + 8192;

        // ---- S = Q K^T (log2 domain; Q pre-scaled) ----
        float s[8][4];
        #pragma unroll
        for (int nf = 0; nf < 8; nf++)
            #pragma unroll
            for (int j = 0; j < 4; j++) s[nf][j] = 0.f;

        #pragma unroll
        for (int kc = 0; kc < 4; kc++) {
            #pragma unroll
            for (int c2 = 0; c2 < 4; c2++) {
                uint32_t h4[4];
                uint32_t off = SWZ((c2*16 + b_r)*128 + kc*32 + b_k);
                LDSM_X4(h4[0], h4[1], h4[2], h4[3], kbh + off);
                MMA_F16(s[c2*2],   qhf[kc], h4[0], h4[1]);
                MMA_F16(s[c2*2+1], qhf[kc], h4[2], h4[3]);
            }
        }

        // ---- causal mask on diagonal tile ----
        if (kt == qt) {
            int r0 = wm + (lane >> 2), r1 = r0 + 8;
            #pragma unroll
            for (int nf = 0; nf < 8; nf++) {
                int c = nf*8 + (lane & 3)*2;
                if (c   > r0) s[nf][0] = -1e30f;
                if (c+1 > r0) s[nf][1] = -1e30f;
                if (c   > r1) s[nf][2] = -1e30f;
                if (c+1 > r1) s[nf][3] = -1e30f;
            }
        }

        // ---- online softmax: max, then f16x2 exp2 ----
        float t0 = -1e30f, t1 = -1e30f;
        #pragma unroll
        for (int nf = 0; nf < 8; nf++) {
            t0 = fmaxf(t0, fmaxf(s[nf][0], s[nf][1]));
            t1 = fmaxf(t1, fmaxf(s[nf][2], s[nf][3]));
        }
        t0 = fmaxf(t0, __shfl_xor_sync(0xffffffffu, t0, 1));
        t0 = fmaxf(t0, __shfl_xor_sync(0xffffffffu, t0, 2));
        t1 = fmaxf(t1, __shfl_xor_sync(0xffffffffu, t1, 1));
        t1 = fmaxf(t1, __shfl_xor_sync(0xffffffffu, t1, 2));
        float mn0 = fmaxf(mrow0, t0), mn1 = fmaxf(mrow1, t1);
        float al0 = fexp2(mrow0 - mn0), al1 = fexp2(mrow1 - mn1);
        mrow0 = mn0; mrow1 = mn1;

        uint32_t p2[8][2];
        #pragma unroll
        for (int nf = 0; nf < 8; nf++) {
            p2[nf][0] = hexp2_2(pack_h2(s[nf][0] - mn0, s[nf][1] - mn0));
            p2[nf][1] = hexp2_2(pack_h2(s[nf][2] - mn1, s[nf][3] - mn1));
        }

        // ---- rescale accumulators ----
        #pragma unroll
        for (int nf = 0; nf < 8; nf++) {
            o[nf][0] *= al0; o[nf][1] *= al0;
            o[nf][2] *= al1; o[nf][3] *= al1;
        }
        osum[0] *= al0; osum[1] *= al0; osum[2] *= al1; osum[3] *= al1;

        // ---- O += P V and row-sum MMA ----
        #pragma unroll
        for (int sk = 0; sk < 4; sk++) {
            uint32_t pha[4];
            pha[0] = p2[sk*2][0];   pha[1] = p2[sk*2][1];
            pha[2] = p2[sk*2+1][0]; pha[3] = p2[sk*2+1][1];
            MMA_F16(osum, pha, ONE2, ONE2);
            #pragma unroll
            for (int c2 = 0; c2 < 4; c2++) {
                uint32_t vh4[4];
                uint32_t off = SWZ((sk*16 + v_r)*128 + c2*32 + v_k);
                LDSM_X4T(vh4[0], vh4[1], vh4[2], vh4[3], vbh + off);
                MMA_F16(o[c2*2],   pha, vh4[0], vh4[1]);
                MMA_F16(o[c2*2+1], pha, vh4[2], vh4[3]);
            }
        }

        __syncthreads();
        if (kt + 2 <= qt) load_kv(kt + 2);
    }

    // ---- epilogue: O / rowsum, write f32 [B,T,C] ----
    float inv0 = 1.0f / osum[0], inv1 = 1.0f / osum[2];
    int r0 = qt*64 + wm + (lane >> 2), r1 = r0 + 8;
    size_t ob = (size_t)b * TT;
    #pragma unroll
    for (int nf = 0; nf < 8; nf++) {
        int d = nf*8 + (lane & 3)*2;
        float2 w0; w0.x = o[nf][0]*inv0; w0.y = o[nf][1]*inv0;
        float2 w1; w1.x = o[nf][2]*inv1; w1.y = o[nf][3]*inv1;
        *(float2*)(O + (ob + r0)*CC + h*DD + d) = w0;
        *(float2*)(O + (ob + r1)*CC + h*DD + d) = w1;
    }
}

#define ATTN_SMEM (1024 + 8192 + 2*16384)
#define MM_SMEM(NT) (1024 + 2*(16384 + (NT)*128))

// ===================== launch ===============================================
extern "C" void kernel_launch(void* const* d_in, const int* in_sizes, int n_in,
                              void* d_out, int out_size)
{
    const float* x    = (const float*)d_in[0];
    const float* ln1g = (const float*)d_in[1];
    const float* ln1b = (const float*)d_in[2];
    const float* wq   = (const float*)d_in[3];
    const float* wk   = (const float*)d_in[4];
    const float* wv   = (const float*)d_in[5];
    const float* ln2g = (const float*)d_in[6];
    const float* ln2b = (const float*)d_in[7];
    const float* wh   = (const float*)d_in[8];
    const float* bh   = (const float*)d_in[9];
    const float* wp   = (const float*)d_in[10];
    const float* bp   = (const float*)d_in[11];
    float* out = (float*)d_out;

    float *att, *x1;
    __half *hh, *h2h, *hidh;
    __half *qh, *kh, *vh;
    __half *wqh, *wkh, *wvh, *whh, *wph;
    cudaGetSymbolAddress((void**)&att,  g_att);
    cudaGetSymbolAddress((void**)&x1,   g_x1);
    cudaGetSymbolAddress((void**)&hh,   g_hh);
    cudaGetSymbolAddress((void**)&h2h,  g_h2h);
    cudaGetSymbolAddress((void**)&hidh, g_hidh);
    cudaGetSymbolAddress((void**)&qh,   g_qh);
    cudaGetSymbolAddress((void**)&kh,   g_kh);
    cudaGetSymbolAddress((void**)&vh,   g_vh);
    cudaGetSymbolAddress((void**)&wqh,  g_wqh);
    cudaGetSymbolAddress((void**)&wkh,  g_wkh);
    cudaGetSymbolAddress((void**)&wvh,  g_wvh);
    cudaGetSymbolAddress((void**)&whh,  g_whh);
    cudaGetSymbolAddress((void**)&wph,  g_wph);

    cudaFuncSetAttribute(attn_kernel,
        cudaFuncAttributeMaxDynamicSharedMemorySize, ATTN_SMEM);
    cudaFuncSetAttribute(mm_kernel<64,3>,
        cudaFuncAttributeMaxDynamicSharedMemorySize, MM_SMEM(64));
    cudaFuncSetAttribute(mm_kernel<64,1>,
        cudaFuncAttributeMaxDynamicSharedMemorySize, MM_SMEM(64));
    cudaFuncSetAttribute(mm_kernel<64,2>,
        cudaFuncAttributeMaxDynamicSharedMemorySize, MM_SMEM(64));

    // weight prep: ALL weights in ONE launch (transpose + fp16 round)
    wprep_kernel<<<6336, 256>>>(wq, wk, wv, wh, wp, wqh, wkh, wvh, whh, wph);

    // LN1 -> fp16
    ln_kernel<false><<<BT, 256>>>(x, x, ln1g, ln1b, hh, nullptr);

    // QKV projection (z = proj*HH + h, NT=64 tiles)
    QKVOut qkv;
    qkv.w0 = wqh; qkv.w1 = wkh; qkv.w2 = wvh;
    qkv.qh = qh; qkv.kh = kh; qkv.vh = vh;
    QKVOut qkv0 = {};
    mm_kernel<64,3><<<dim3(1, BT/128, 3*HH), 256, MM_SMEM(64)>>>(
        hh, CC, 0, nullptr, 0,
        nullptr, 0, 0, CC, nullptr, nullptr, nullptr, 0, qkv);

    // HMMA flash attention (round-11 shape: 64-row q tiles, reg-resident Q)
    attn_kernel<<<dim3(TT/64, BB*HH), 128, ATTN_SMEM>>>(qh, kh, vh, att);

    // residual + LN2 -> fp16 (+x1)
    ln_kernel<true><<<BT, 256>>>(x, att, ln2g, ln2b, h2h, x1);

    // MLP (HMMA); both layers NT=64 for wave balance
    // MLP1: grid (48,32)=1536 CTAs @ 4 CTAs/SM -> 2.6 waves (was 1.73 @ NT=128)
    mm_kernel<64,1><<<dim3(C4/64, BT/128, 1), 256, MM_SMEM(64)>>>(
        h2h, CC, 0, whh, 0, nullptr, 0, 0, CC, bh, nullptr,
        hidh, C4, qkv0);
    // MLP2: grid (12,32)=384 CTAs (proven round 13)
    mm_kernel<64,2><<<dim3(CC/64, BT/128, 1), 256, MM_SMEM(64)>>>(
        hidh, C4, 0, wph, 0, out, CC, 0, C4, bp, x1,
        nullptr, 0, qkv0);
}

// round 15
// speedup vs baseline: 1.0072x; 1.0072x over previous
#include <cuda_runtime.h>
#include <cuda_fp16.h>
#include <cstdint>

#define BB 2
#define TT 2048
#define CC 768
#define HH 12
#define DD 64
#define BT (BB*TT)          // 4096 rows
#define C4 (4*CC)           // 3072
#define SCALE_L2E (0.03608439182435161f * 1.4426950408889634f)  // 1/sqrt(C)*log2(e)

// ===================== PTX helpers (sm_80-compatible only) ==================
__device__ __forceinline__ uint32_t smem_u32(const void* p) {
    uint32_t a;
    asm("{ .reg .u64 t; cvta.to.shared.u64 t, %1; cvt.u32.u64 %0, t; }"
        : "=r"(a) : "l"(p));
    return a;
}

#define CP16(s, g) \
    asm volatile("cp.async.cg.shared.global [%0], [%1], 16;" :: "r"(s), "l"(g))
#define CP_COMMIT() asm volatile("cp.async.commit_group;" ::: "memory")
#define CP_WAIT(n)  asm volatile("cp.async.wait_group %0;" :: "n"(n) : "memory")

#define LDSM_X4(r0, r1, r2, r3, a) \
    asm volatile("ldmatrix.sync.aligned.m8n8.x4.shared.b16 {%0,%1,%2,%3}, [%4];" \
        : "=r"(r0), "=r"(r1), "=r"(r2), "=r"(r3) : "r"(a))

#define LDSM_X4T(r0, r1, r2, r3, a) \
    asm volatile("ldmatrix.sync.aligned.m8n8.x4.trans.shared.b16 {%0,%1,%2,%3}, [%4];" \
        : "=r"(r0), "=r"(r1), "=r"(r2), "=r"(r3) : "r"(a))

#define MMA_F16(d, a, b0, b1) \
    asm volatile("mma.sync.aligned.m16n8k16.row.col.f32.f16.f16.f32 " \
        "{%0,%1,%2,%3}, {%4,%5,%6,%7}, {%8,%9}, {%0,%1,%2,%3};" \
        : "+f"((d)[0]), "+f"((d)[1]), "+f"((d)[2]), "+f"((d)[3]) \
        : "r"((a)[0]), "r"((a)[1]), "r"((a)[2]), "r"((a)[3]), "r"(b0), "r"(b1))

#define SWZ(x) ((x) ^ (((x) >> 3) & 0x70))

__device__ __forceinline__ uint32_t pack_h2(float lo, float hi) {
    uint32_t r;
    asm("cvt.rn.f16x2.f32 %0, %1, %2;" : "=r"(r) : "f"(hi), "f"(lo));
    return r;
}
__device__ __forceinline__ uint32_t hexp2_2(uint32_t a) {
    uint32_t r;
    asm("ex2.approx.f16x2 %0, %1;" : "=r"(r) : "r"(a));
    return r;
}
__device__ __forceinline__ float fexp2(float x) {
    float r;
    asm("ex2.approx.ftz.f32 %0, %1;" : "=f"(r) : "f"(x));
    return r;
}

// ===================== scratch (static device memory) ======================
__device__ __half g_atth[BT*CC];            // attention out, fp16
__device__ float g_x1 [BT*CC];
__device__ __half g_hh [BT*CC];
__device__ __half g_h2h[BT*CC];
__device__ __half g_hidh[(size_t)BT*C4];
// qkv, layout [B,H,T,D], fp16; Q pre-scaled by SCALE_L2E (log2 domain)
__device__ __half g_qh[BT*CC];
__device__ __half g_kh[BT*CC];
__device__ __half g_vh[BT*CC];
__device__ __half g_wqh[HH*DD*CC];
__device__ __half g_wkh[HH*DD*CC];
__device__ __half g_wvh[HH*DD*CC];
__device__ __half g_whh[(size_t)C4*CC];
__device__ __half g_wph[(size_t)CC*C4];

struct QKVOut {
    const __half *w0, *w1, *w2;
    __half *qh, *kh, *vh;
};

// ===================== fused weight prep (ALL weights, ONE launch) =========
__global__ __launch_bounds__(256) void wprep_kernel(
    const float* __restrict__ wq, const float* __restrict__ wk,
    const float* __restrict__ wv, const float* __restrict__ wh,
    const float* __restrict__ wp,
    __half* __restrict__ wqh, __half* __restrict__ wkh,
    __half* __restrict__ wvh, __half* __restrict__ whh,
    __half* __restrict__ wph)
{
    int id = blockIdx.x;
    const float* in; __half* oh;
    int R, Cn, x, y; long zo = 0;
    if (id < 1728) {                 // wq/wk/wv: 3 sections x 12 heads x (2x24)
        int sec = id / 576, r = id % 576;
        int z = r / 48, rr = r % 48;
        x = rr & 1; y = rr >> 1;
        R = CC; Cn = DD;
        zo = (long)z * CC * DD;
        in = (sec == 0) ? wq : (sec == 1) ? wk : wv;
        oh = (sec == 0) ? wqh : (sec == 1) ? wkh : wvh;
    } else if (id < 4032) {          // wh: 96 x-tiles, 24 y-tiles
        int r = id - 1728;
        x = r % 96; y = r / 96;
        R = CC; Cn = C4; in = wh; oh = whh;
    } else {                         // wp: 24 x-tiles, 96 y-tiles
        int r = id - 4032;
        x = r % 24; y = r / 24;
        R = C4; Cn = CC; in = wp; oh = wph;
    }

    __shared__ float ts[32][33];
    int r0 = y * 32, c0 = x * 32;
    int tx = threadIdx.x & 31, ty = threadIdx.x >> 5;
    #pragma unroll
    for (int i = 0; i < 4; i++) {
        int r = r0 + ty + i*8;
        ts[ty + i*8][tx] = in[zo + (size_t)r*Cn + c0 + tx];
    }
    __syncthreads();
    #pragma unroll
    for (int i = 0; i < 4; i++) {
        int cc = ty + i*8;
        size_t oi = zo + (size_t)(c0 + cc)*R + r0 + tx;
        oh[oi] = __float2half(ts[tx][cc]);
    }
}

// ===================== LayerNorm -> fp16 (+opt fp16 residual) ==============
template<bool ADD>
__global__ __launch_bounds__(256) void ln_kernel(
    const float* __restrict__ x, const __half* __restrict__ addh,
    const float* __restrict__ g, const float* __restrict__ be,
    __half* __restrict__ oh, float* __restrict__ outsum)
{
    int row = blockIdx.x;
    int tid = threadIdx.x;
    const float* xr = x + (size_t)row*CC;
    const __half* ar = addh + (size_t)row*CC;
    float v[3]; float s = 0.f, sq = 0.f;
    #pragma unroll
    for (int i = 0; i < 3; i++) {
        int c = tid + i*256;
        float val = xr[c];
        if (ADD) val += __half2float(ar[c]);
        v[i] = val; s += val; sq = fmaf(val, val, sq);
    }
    #pragma unroll
    for (int o = 16; o > 0; o >>= 1) {
        s  += __shfl_down_sync(0xffffffffu, s,  o);
        sq += __shfl_down_sync(0xffffffffu, sq, o);
    }
    __shared__ float rs[8], rq[8], stat[2];
    if ((tid & 31) == 0) { rs[tid>>5] = s; rq[tid>>5] = sq; }
    __syncthreads();
    if (tid == 0) {
        float ts = 0.f, tq = 0.f;
        #pragma unroll
        for (int i = 0; i < 8; i++) { ts += rs[i]; tq += rq[i]; }
        float mu  = ts * (1.0f/CC);
        float var = tq * (1.0f/CC) - mu*mu;
        stat[0] = mu; stat[1] = rsqrtf(var + 1e-5f);
    }
    __syncthreads();
    float mu = stat[0], rstd = stat[1];
    #pragma unroll
    for (int i = 0; i < 3; i++) {
        int c = tid + i*256;
        float val = (v[i]-mu)*rstd*g[c] + be[c];
        oh[(size_t)row*CC + c] = __float2half(val);
        if (ADD) outsum[(size_t)row*CC + c] = v[i];
    }
}

// ===================== HMMA (mma.sync) GEMM =================================
// C[M,N] = A[M,K] * B[N,K]^T, fp16 1-term.
// MODE 1: +bias, ReLU, store fp16.  MODE 2: +bias +residual, f32 store.
// MODE 3: fused QKV (z = proj*HH + h), out fp16 [B,H,T,D], Q pre-scaled.
template<int NT, int MODE>
__global__ __launch_bounds__(256)
void mm_kernel(
    const __half* __restrict__ Ah, int lda, long strideA,
    const __half* __restrict__ Bh, long strideB,
    float* __restrict__ C, int ldc, long strideC,
    int Ktot,
    const float* __restrict__ bias, const float* __restrict__ res,
    __half* __restrict__ Oh, int ldo,
    QKVOut qkv)
{
    static_assert(NT == 64 || NT == 128, "NT");
    constexpr int SA_H = 0;
    constexpr int SB_H = 16384;
    constexpr int STAGE = 16384 + NT*128;
    constexpr int NB = NT/32;
    constexpr int NW = NT/2;
    constexpr int NT8 = NW/8;
    constexpr int NT16 = NW/16;

    extern __shared__ char smraw[];
    char* sm = (char*)(((uintptr_t)smraw + 1023) & ~(uintptr_t)1023);
    uint32_t sm32 = smem_u32(sm);

    int tid = threadIdx.x;
    int wid = tid >> 5, lane = tid & 31;
    int z = blockIdx.z;
    int proj = 0, hsel = 0;
    if (MODE == 3) {
        proj = z / HH; hsel = z % HH;
        const __half* w = (proj == 0) ? qkv.w0 : (proj == 1) ? qkv.w1 : qkv.w2;
        Bh = w + (size_t)hsel*CC*DD;
    } else {
        Ah += (size_t)z * strideA;
        Bh += (size_t)z * strideB;
        if (MODE == 2) C += (size_t)z * strideC;
    }
    int bm = blockIdx.y * 128, bn = blockIdx.x * NT;

    int wm = (wid & 3) * 32;
    int wn = (wid >> 2) * NW;

    int lr = lane & 7;
    int a_r = lr + ((lane & 8) ? 8 : 0);
    int a_k = (lane & 16) ? 16 : 0;
    int b_r = lr + ((lane & 16) ? 8 : 0);
    int b_k = (lane & 8) ? 16 : 0;

    int g_row = tid >> 3, g_ch = tid & 7;

    float acc[2][NT8][4];
    #pragma unroll
    for (int mt = 0; mt < 2; mt++)
        #pragma unroll
        for (int nt = 0; nt < NT8; nt++)
            #pragma unroll
            for (int j = 0; j < 4; j++) acc[mt][nt][j] = 0.f;

    int nk = Ktot >> 6;

    auto load_stage = [&](int t) {
        int stg = (t & 1) * STAGE;
        int k0 = t << 6;
        #pragma unroll
        for (int i = 0; i < 4; i++) {
            int row = g_row + i*32;
            uint32_t so = sm32 + stg + SWZ(row*128 + g_ch*16);
            CP16(so + SA_H, Ah + (size_t)(bm+row)*lda + k0 + g_ch*8);
        }
        #pragma unroll
        for (int i = 0; i < NB; i++) {
            int row = g_row + i*32;
            uint32_t so = sm32 + stg + SWZ(row*128 + g_ch*16);
            CP16(so + SB_H, Bh + (size_t)(bn+row)*lda + k0 + g_ch*8);
        }
        CP_COMMIT();
    };

    load_stage(0);
    if (nk > 1) load_stage(1);

    for (int t = 0; t < nk; t++) {
        if (t < nk - 1) { CP_WAIT(1); } else { CP_WAIT(0); }
        __syncthreads();
        int stg = (t & 1) * STAGE;
        uint32_t baseA_h = sm32 + stg + SA_H;
        uint32_t baseB_h = sm32 + stg + SB_H;

        #pragma unroll
        for (int kt = 0; kt < 4; kt++) {
            int kb = kt*32;
            uint32_t ah[2][4];
            #pragma unroll
            for (int mt = 0; mt < 2; mt++) {
                uint32_t off = SWZ((wm + mt*16 + a_r)*128 + kb + a_k);
                LDSM_X4(ah[mt][0], ah[mt][1], ah[mt][2], ah[mt][3], baseA_h + off);
            }
            uint32_t bh[NT16][4];
            #pragma unroll
            for (int n2 = 0; n2 < NT16; n2++) {
                uint32_t off = SWZ((wn + n2*16 + b_r)*128 + kb + b_k);
                LDSM_X4(bh[n2][0], bh[n2][1], bh[n2][2], bh[n2][3], baseB_h + off);
            }
            #pragma unroll
            for (int mt = 0; mt < 2; mt++) {
                #pragma unroll
                for (int n2 = 0; n2 < NT16; n2++) {
                    MMA_F16(acc[mt][n2*2],   ah[mt], bh[n2][0], bh[n2][1]);
                    MMA_F16(acc[mt][n2*2+1], ah[mt], bh[n2][2], bh[n2][3]);
                }
            }
        }
        __syncthreads();
        if (t + 2 < nk) load_stage(t + 2);
    }

    // ---- epilogue ----
    int mrow0 = bm + wm + (lane >> 2);
    int ncol0 = bn + wn + (lane & 3) * 2;
    #pragma unroll
    for (int mt = 0; mt < 2; mt++) {
        #pragma unroll
        for (int half = 0; half < 2; half++) {
            int m = mrow0 + mt*16 + half*8;
            #pragma unroll
            for (int nt = 0; nt < NT8; nt++) {
                int n = ncol0 + nt*8;
                float v0 = acc[mt][nt][half*2];
                float v1 = acc[mt][nt][half*2+1];
                if (MODE == 1) {
                    v0 = fmaxf(v0 + bias[n],   0.f);
                    v1 = fmaxf(v1 + bias[n+1], 0.f);
                    __half2 hh2;
                    hh2.x = __float2half(v0); hh2.y = __float2half(v1);
                    *(__half2*)(Oh + (size_t)m*ldo + n) = hh2;
                } else if (MODE == 2) {
                    float2 rr = *(const float2*)(res + (size_t)m*ldc + n);
                    float2 o;
                    o.x = v0 + bias[n]   + rr.x;
                    o.y = v1 + bias[n+1] + rr.y;
                    *(float2*)(C + (size_t)m*ldc + n) = o;
                } else if (MODE == 3) {
                    if (proj == 0) { v0 *= SCALE_L2E; v1 *= SCALE_L2E; }
                    __half2 hh2;
                    hh2.x = __float2half(v0); hh2.y = __float2half(v1);
                    __half* p = (proj == 0) ? qkv.qh : (proj == 1) ? qkv.kh : qkv.vh;
                    size_t o = (((size_t)(m >> 11)*HH + hsel)*TT + (m & (TT-1)))*DD + n;
                    *(__half2*)(p + o) = hh2;
                }
            }
        }
    }
}

// ===================== HMMA flash attention (causal) ========================
// ROUND-11 PROVEN SHAPE: 128 threads (4 warps), CTA owns 64 q rows, warp 16.
// Q fragments register-resident; fp16 1-term; Q pre-scaled (log2 domain);
// f16x2 ex2; P = fp16 A-frags; row sums via all-ones B-frag MMA.
// CHANGE: output written as fp16 (halves att intermediate traffic).
__global__ __launch_bounds__(128) void attn_kernel(
    const __half* __restrict__ Qh, const __half* __restrict__ Kh,
    const __half* __restrict__ Vh, __half* __restrict__ O)
{
    extern __shared__ char smraw[];
    char* sm = (char*)(((uintptr_t)smraw + 1023) & ~(uintptr_t)1023);
    uint32_t sm32 = smem_u32(sm);

    constexpr int QH_O = 0, STG_O = 8192, STG_SZ = 16384;
    constexpr uint32_t ONE2 = 0x3C003C00u;   // half2(1.0, 1.0)

    int qt = gridDim.x - 1 - (int)blockIdx.x;   // longest first
    int bh = blockIdx.y;
    int b = bh / HH, h = bh % HH;
    int tid = threadIdx.x, wid = tid >> 5, lane = tid & 31;
    size_t base = (size_t)bh * TT * DD;

    // ---- Q tile: 64 rows x 128B = 512 chunks = 128 thr x 4 iters ----
    #pragma unroll
    for (int i = 0; i < 4; i++) {
        int idx = tid + i*128; int row = idx >> 3, ch = idx & 7;
        uint32_t so = sm32 + SWZ(row*128 + ch*16);
        size_t ga = base + (size_t)(qt*64 + row)*DD + ch*8;
        CP16(so + QH_O, Qh + ga);
    }
    auto load_kv = [&](int kt) {
        int stg = STG_O + (kt & 1) * STG_SZ;
        #pragma unroll
        for (int i = 0; i < 4; i++) {
            int idx = tid + i*128; int row = idx >> 3, ch = idx & 7;
            uint32_t so = sm32 + stg + SWZ(row*128 + ch*16);
            size_t ga = base + (size_t)(kt*64 + row)*DD + ch*8;
            CP16(so,        Kh + ga);
            CP16(so + 8192, Vh + ga);
        }
        CP_COMMIT();
    };
    load_kv(0);
    if (qt >= 1) load_kv(1);

    int lr = lane & 7;
    int a_r = lr + ((lane & 8) ? 8 : 0);
    int a_k = (lane & 16) ? 16 : 0;
    int b_r = lr + ((lane & 16) ? 8 : 0);
    int b_k = (lane & 8) ? 16 : 0;
    int v_r = lr + ((lane & 8) ? 8 : 0);
    int v_k = (lane & 16) ? 16 : 0;
    int wm = wid * 16;

    float o[8][4];
    #pragma unroll
    for (int nf = 0; nf < 8; nf++)
        #pragma unroll
        for (int j = 0; j < 4; j++) o[nf][j] = 0.f;
    float osum[4] = {0.f, 0.f, 0.f, 0.f};
    float mrow0 = -1e30f, mrow1 = -1e30f;

    if (qt >= 1) { CP_WAIT(1); } else { CP_WAIT(0); }
    __syncthreads();

    uint32_t qhf[4][4];
    #pragma unroll
    for (int kc = 0; kc < 4; kc++) {
        uint32_t off = SWZ((wm + a_r)*128 + kc*32 + a_k);
        LDSM_X4(qhf[kc][0], qhf[kc][1], qhf[kc][2], qhf[kc][3], sm32 + QH_O + off);
    }

    for (int kt = 0; kt <= qt; kt++) {
        if (kt > 0) {
            if (kt < qt) { CP_WAIT(1); } else { CP_WAIT(0); }
            __syncthreads();
        }
        uint32_t kbh = sm32 + STG_O + (kt & 1)*STG_SZ;
        uint32_t vbh = kbh + 8192;

        // ---- S = Q K^T (log2 domain; Q pre-scaled) ----
        float s[8][4];
        #pragma unroll
        for (int nf = 0; nf < 8; nf++)
            #pragma unroll
            for (int j = 0; j < 4; j++) s[nf][j] = 0.f;

        #pragma unroll
        for (int kc = 0; kc < 4; kc++) {
            #pragma unroll
            for (int c2 = 0; c2 < 4; c2++) {
                uint32_t h4[4];
                uint32_t off = SWZ((c2*16 + b_r)*128 + kc*32 + b_k);
                LDSM_X4(h4[0], h4[1], h4[2], h4[3], kbh + off);
                MMA_F16(s[c2*2],   qhf[kc], h4[0], h4[1]);
                MMA_F16(s[c2*2+1], qhf[kc], h4[2], h4[3]);
            }
        }

        // ---- causal mask on diagonal tile ----
        if (kt == qt) {
            int r0 = wm + (lane >> 2), r1 = r0 + 8;
            #pragma unroll
            for (int nf = 0; nf < 8; nf++) {
                int c = nf*8 + (lane & 3)*2;
                if (c   > r0) s[nf][0] = -1e30f;
                if (c+1 > r0) s[nf][1] = -1e30f;
                if (c   > r1) s[nf][2] = -1e30f;
                if (c+1 > r1) s[nf][3] = -1e30f;
            }
        }

        // ---- online softmax: max, then f16x2 exp2 ----
        float t0 = -1e30f, t1 = -1e30f;
        #pragma unroll
        for (int nf = 0; nf < 8; nf++) {
            t0 = fmaxf(t0, fmaxf(s[nf][0], s[nf][1]));
            t1 = fmaxf(t1, fmaxf(s[nf][2], s[nf][3]));
        }
        t0 = fmaxf(t0, __shfl_xor_sync(0xffffffffu, t0, 1));
        t0 = fmaxf(t0, __shfl_xor_sync(0xffffffffu, t0, 2));
        t1 = fmaxf(t1, __shfl_xor_sync(0xffffffffu, t1, 1));
        t1 = fmaxf(t1, __shfl_xor_sync(0xffffffffu, t1, 2));
        float mn0 = fmaxf(mrow0, t0), mn1 = fmaxf(mrow1, t1);
        float al0 = fexp2(mrow0 - mn0), al1 = fexp2(mrow1 - mn1);
        mrow0 = mn0; mrow1 = mn1;

        uint32_t p2[8][2];
        #pragma unroll
        for (int nf = 0; nf < 8; nf++) {
            p2[nf][0] = hexp2_2(pack_h2(s[nf][0] - mn0, s[nf][1] - mn0));
            p2[nf][1] = hexp2_2(pack_h2(s[nf][2] - mn1, s[nf][3] - mn1));
        }

        // ---- rescale accumulators ----
        #pragma unroll
        for (int nf = 0; nf < 8; nf++) {
            o[nf][0] *= al0; o[nf][1] *= al0;
            o[nf][2] *= al1; o[nf][3] *= al1;
        }
        osum[0] *= al0; osum[1] *= al0; osum[2] *= al1; osum[3] *= al1;

        // ---- O += P V and row-sum MMA ----
        #pragma unroll
        for (int sk = 0; sk < 4; sk++) {
            uint32_t pha[4];
            pha[0] = p2[sk*2][0];   pha[1] = p2[sk*2][1];
            pha[2] = p2[sk*2+1][0]; pha[3] = p2[sk*2+1][1];
            MMA_F16(osum, pha, ONE2, ONE2);
            #pragma unroll
            for (int c2 = 0; c2 < 4; c2++) {
                uint32_t vh4[4];
                uint32_t off = SWZ((sk*16 + v_r)*128 + c2*32 + v_k);
                LDSM_X4T(vh4[0], vh4[1], vh4[2], vh4[3], vbh + off);
                MMA_F16(o[c2*2],   pha, vh4[0], vh4[1]);
                MMA_F16(o[c2*2+1], pha, vh4[2], vh4[3]);
            }
        }

        __syncthreads();
        if (kt + 2 <= qt) load_kv(kt + 2);
    }

    // ---- epilogue: O / rowsum, write fp16 [B,T,C] ----
    float inv0 = 1.0f / osum[0], inv1 = 1.0f / osum[2];
    int r0 = qt*64 + wm + (lane >> 2), r1 = r0 + 8;
    size_t ob = (size_t)b * TT;
    #pragma unroll
    for (int nf = 0; nf < 8; nf++) {
        int d = nf*8 + (lane & 3)*2;
        __half2 w0, w1;
        w0.x = __float2half(o[nf][0]*inv0); w0.y = __float2half(o[nf][1]*inv0);
        w1.x = __float2half(o[nf][2]*inv1); w1.y = __float2half(o[nf][3]*inv1);
        *(__half2*)(O + (ob + r0)*CC + h*DD + d) = w0;
        *(__half2*)(O + (ob + r1)*CC + h*DD + d) = w1;
    }
}

#define ATTN_SMEM (1024 + 8192 + 2*16384)
#define MM_SMEM(NT) (1024 + 2*(16384 + (NT)*128))

// ===================== launch ===============================================
extern "C" void kernel_launch(void* const* d_in, const int* in_sizes, int n_in,
                              void* d_out, int out_size)
{
    const float* x    = (const float*)d_in[0];
    const float* ln1g = (const float*)d_in[1];
    const float* ln1b = (const float*)d_in[2];
    const float* wq   = (const float*)d_in[3];
    const float* wk   = (const float*)d_in[4];
    const float* wv   = (const float*)d_in[5];
    const float* ln2g = (const float*)d_in[6];
    const float* ln2b = (const float*)d_in[7];
    const float* wh   = (const float*)d_in[8];
    const float* bh   = (const float*)d_in[9];
    const float* wp   = (const float*)d_in[10];
    const float* bp   = (const float*)d_in[11];
    float* out = (float*)d_out;

    float *x1;
    __half *atth, *hh, *h2h, *hidh;
    __half *qh, *kh, *vh;
    __half *wqh, *wkh, *wvh, *whh, *wph;
    cudaGetSymbolAddress((void**)&atth, g_atth);
    cudaGetSymbolAddress((void**)&x1,   g_x1);
    cudaGetSymbolAddress((void**)&hh,   g_hh);
    cudaGetSymbolAddress((void**)&h2h,  g_h2h);
    cudaGetSymbolAddress((void**)&hidh, g_hidh);
    cudaGetSymbolAddress((void**)&qh,   g_qh);
    cudaGetSymbolAddress((void**)&kh,   g_kh);
    cudaGetSymbolAddress((void**)&vh,   g_vh);
    cudaGetSymbolAddress((void**)&wqh,  g_wqh);
    cudaGetSymbolAddress((void**)&wkh,  g_wkh);
    cudaGetSymbolAddress((void**)&wvh,  g_wvh);
    cudaGetSymbolAddress((void**)&whh,  g_whh);
    cudaGetSymbolAddress((void**)&wph,  g_wph);

    cudaFuncSetAttribute(attn_kernel,
        cudaFuncAttributeMaxDynamicSharedMemorySize, ATTN_SMEM);
    cudaFuncSetAttribute(mm_kernel<64,3>,
        cudaFuncAttributeMaxDynamicSharedMemorySize, MM_SMEM(64));
    cudaFuncSetAttribute(mm_kernel<128,1>,
        cudaFuncAttributeMaxDynamicSharedMemorySize, MM_SMEM(128));
    cudaFuncSetAttribute(mm_kernel<64,2>,
        cudaFuncAttributeMaxDynamicSharedMemorySize, MM_SMEM(64));

    // weight prep: ALL weights in ONE launch (transpose + fp16 round)
    wprep_kernel<<<6336, 256>>>(wq, wk, wv, wh, wp, wqh, wkh, wvh, whh, wph);

    // LN1 -> fp16
    ln_kernel<false><<<BT, 256>>>(x, nullptr, ln1g, ln1b, hh, nullptr);

    // QKV projection (z = proj*HH + h, NT=64 tiles)
    QKVOut qkv;
    qkv.w0 = wqh; qkv.w1 = wkh; qkv.w2 = wvh;
    qkv.qh = qh; qkv.kh = kh; qkv.vh = vh;
    QKVOut qkv0 = {};
    mm_kernel<64,3><<<dim3(1, BT/128, 3*HH), 256, MM_SMEM(64)>>>(
        hh, CC, 0, nullptr, 0,
        nullptr, 0, 0, CC, nullptr, nullptr, nullptr, 0, qkv);

    // HMMA flash attention (round-11 shape; fp16 output)
    attn_kernel<<<dim3(TT/64, BB*HH), 128, ATTN_SMEM>>>(qh, kh, vh, atth);

    // residual (fp16 att) + LN2 -> fp16 (+x1 f32)
    ln_kernel<true><<<BT, 256>>>(x, atth, ln2g, ln2b, h2h, x1);

    // MLP (HMMA); MLP1 NT=128 (round-13 champion), MLP2 NT=64 (proven)
    mm_kernel<128,1><<<dim3(C4/128, BT/128, 1), 256, MM_SMEM(128)>>>(
        h2h, CC, 0, whh, 0, nullptr, 0, 0, CC, bh, nullptr,
        hidh, C4, qkv0);
    mm_kernel<64,2><<<dim3(CC/64, BT/128, 1), 256, MM_SMEM(64)>>>(
        hidh, C4, 0, wph, 0, out, CC, 0, C4, bp, x1,
        nullptr, 0, qkv0);
}

// round 16
// speedup vs baseline: 1.0417x; 1.0342x over previous
#include <cuda_runtime.h>
#include <cuda_fp16.h>
#include <cstdint>

#define BB 2
#define TT 2048
#define CC 768
#define HH 12
#define DD 64
#define BT (BB*TT)          // 4096 rows
#define C4 (4*CC)           // 3072
#define SCALE_L2E (0.03608439182435161f * 1.4426950408889634f)  // 1/sqrt(C)*log2(e)

// ===================== PTX helpers (sm_80-compatible only) ==================
__device__ __forceinline__ uint32_t smem_u32(const void* p) {
    uint32_t a;
    asm("{ .reg .u64 t; cvta.to.shared.u64 t, %1; cvt.u32.u64 %0, t; }"
        : "=r"(a) : "l"(p));
    return a;
}

#define CP16(s, g) \
    asm volatile("cp.async.cg.shared.global [%0], [%1], 16;" :: "r"(s), "l"(g))
#define CP_COMMIT() asm volatile("cp.async.commit_group;" ::: "memory")
#define CP_WAIT(n)  asm volatile("cp.async.wait_group %0;" :: "n"(n) : "memory")

#define LDSM_X4(r0, r1, r2, r3, a) \
    asm volatile("ldmatrix.sync.aligned.m8n8.x4.shared.b16 {%0,%1,%2,%3}, [%4];" \
        : "=r"(r0), "=r"(r1), "=r"(r2), "=r"(r3) : "r"(a))

#define LDSM_X4T(r0, r1, r2, r3, a) \
    asm volatile("ldmatrix.sync.aligned.m8n8.x4.trans.shared.b16 {%0,%1,%2,%3}, [%4];" \
        : "=r"(r0), "=r"(r1), "=r"(r2), "=r"(r3) : "r"(a))

#define MMA_F16(d, a, b0, b1) \
    asm volatile("mma.sync.aligned.m16n8k16.row.col.f32.f16.f16.f32 " \
        "{%0,%1,%2,%3}, {%4,%5,%6,%7}, {%8,%9}, {%0,%1,%2,%3};" \
        : "+f"((d)[0]), "+f"((d)[1]), "+f"((d)[2]), "+f"((d)[3]) \
        : "r"((a)[0]), "r"((a)[1]), "r"((a)[2]), "r"((a)[3]), "r"(b0), "r"(b1))

#define SWZ(x) ((x) ^ (((x) >> 3) & 0x70))

__device__ __forceinline__ uint32_t pack_h2(float lo, float hi) {
    uint32_t r;
    asm("cvt.rn.f16x2.f32 %0, %1, %2;" : "=r"(r) : "f"(hi), "f"(lo));
    return r;
}
__device__ __forceinline__ uint32_t hexp2_2(uint32_t a) {
    uint32_t r;
    asm("ex2.approx.f16x2 %0, %1;" : "=r"(r) : "r"(a));
    return r;
}
__device__ __forceinline__ float fexp2(float x) {
    float r;
    asm("ex2.approx.ftz.f32 %0, %1;" : "=f"(r) : "f"(x));
    return r;
}

// ===================== scratch (static device memory) ======================
__device__ __half g_atth[BT*CC];            // attention out, fp16
__device__ float g_x1 [BT*CC];
__device__ __half g_hh [BT*CC];
__device__ __half g_h2h[BT*CC];
__device__ __half g_hidh[(size_t)BT*C4];
// qkv, layout [B,H,T,D], fp16; Q pre-scaled by SCALE_L2E (log2 domain)
__device__ __half g_qh[BT*CC];
__device__ __half g_kh[BT*CC];
__device__ __half g_vh[BT*CC];
__device__ __half g_wqh[HH*DD*CC];
__device__ __half g_wkh[HH*DD*CC];
__device__ __half g_wvh[HH*DD*CC];
__device__ __half g_whh[(size_t)C4*CC];
__device__ __half g_wph[(size_t)CC*C4];

struct QKVOut {
    const __half *w0, *w1, *w2;
    __half *qh, *kh, *vh;
};

// ===================== fused weight prep (ALL weights, ONE launch) =========
__global__ __launch_bounds__(256) void wprep_kernel(
    const float* __restrict__ wq, const float* __restrict__ wk,
    const float* __restrict__ wv, const float* __restrict__ wh,
    const float* __restrict__ wp,
    __half* __restrict__ wqh, __half* __restrict__ wkh,
    __half* __restrict__ wvh, __half* __restrict__ whh,
    __half* __restrict__ wph)
{
    int id = blockIdx.x;
    const float* in; __half* oh;
    int R, Cn, x, y; long zo = 0;
    if (id < 1728) {                 // wq/wk/wv: 3 sections x 12 heads x (2x24)
        int sec = id / 576, r = id % 576;
        int z = r / 48, rr = r % 48;
        x = rr & 1; y = rr >> 1;
        R = CC; Cn = DD;
        zo = (long)z * CC * DD;
        in = (sec == 0) ? wq : (sec == 1) ? wk : wv;
        oh = (sec == 0) ? wqh : (sec == 1) ? wkh : wvh;
    } else if (id < 4032) {          // wh: 96 x-tiles, 24 y-tiles
        int r = id - 1728;
        x = r % 96; y = r / 96;
        R = CC; Cn = C4; in = wh; oh = whh;
    } else {                         // wp: 24 x-tiles, 96 y-tiles
        int r = id - 4032;
        x = r % 24; y = r / 24;
        R = C4; Cn = CC; in = wp; oh = wph;
    }

    __shared__ float ts[32][33];
    int r0 = y * 32, c0 = x * 32;
    int tx = threadIdx.x & 31, ty = threadIdx.x >> 5;
    #pragma unroll
    for (int i = 0; i < 4; i++) {
        int r = r0 + ty + i*8;
        ts[ty + i*8][tx] = in[zo + (size_t)r*Cn + c0 + tx];
    }
    __syncthreads();
    #pragma unroll
    for (int i = 0; i < 4; i++) {
        int cc = ty + i*8;
        size_t oi = zo + (size_t)(c0 + cc)*R + r0 + tx;
        oh[oi] = __float2half(ts[tx][cc]);
    }
}

// ===================== LayerNorm -> fp16 (+opt fp16 residual) ==============
template<bool ADD>
__global__ __launch_bounds__(256) void ln_kernel(
    const float* __restrict__ x, const __half* __restrict__ addh,
    const float* __restrict__ g, const float* __restrict__ be,
    __half* __restrict__ oh, float* __restrict__ outsum)
{
    int row = blockIdx.x;
    int tid = threadIdx.x;
    const float* xr = x + (size_t)row*CC;
    const __half* ar = addh + (size_t)row*CC;
    float v[3]; float s = 0.f, sq = 0.f;
    #pragma unroll
    for (int i = 0; i < 3; i++) {
        int c = tid + i*256;
        float val = xr[c];
        if (ADD) val += __half2float(ar[c]);
        v[i] = val; s += val; sq = fmaf(val, val, sq);
    }
    #pragma unroll
    for (int o = 16; o > 0; o >>= 1) {
        s  += __shfl_down_sync(0xffffffffu, s,  o);
        sq += __shfl_down_sync(0xffffffffu, sq, o);
    }
    __shared__ float rs[8], rq[8], stat[2];
    if ((tid & 31) == 0) { rs[tid>>5] = s; rq[tid>>5] = sq; }
    __syncthreads();
    if (tid == 0) {
        float ts = 0.f, tq = 0.f;
        #pragma unroll
        for (int i = 0; i < 8; i++) { ts += rs[i]; tq += rq[i]; }
        float mu  = ts * (1.0f/CC);
        float var = tq * (1.0f/CC) - mu*mu;
        stat[0] = mu; stat[1] = rsqrtf(var + 1e-5f);
    }
    __syncthreads();
    float mu = stat[0], rstd = stat[1];
    #pragma unroll
    for (int i = 0; i < 3; i++) {
        int c = tid + i*256;
        float val = (v[i]-mu)*rstd*g[c] + be[c];
        oh[(size_t)row*CC + c] = __float2half(val);
        if (ADD) outsum[(size_t)row*CC + c] = v[i];
    }
}

// ===================== HMMA (mma.sync) GEMM =================================
// C[M,N] = A[M,K] * B[N,K]^T, fp16 1-term.
// MODE 1: +bias, ReLU, store fp16.  MODE 2: +bias +residual, f32 store.
// MODE 3: fused QKV (z = proj*HH + h), out fp16 [B,H,T,D], Q pre-scaled.
template<int NT, int MODE>
__global__ __launch_bounds__(256)
void mm_kernel(
    const __half* __restrict__ Ah, int lda, long strideA,
    const __half* __restrict__ Bh, long strideB,
    float* __restrict__ C, int ldc, long strideC,
    int Ktot,
    const float* __restrict__ bias, const float* __restrict__ res,
    __half* __restrict__ Oh, int ldo,
    QKVOut qkv)
{
    static_assert(NT == 64 || NT == 128, "NT");
    constexpr int SA_H = 0;
    constexpr int SB_H = 16384;
    constexpr int STAGE = 16384 + NT*128;
    constexpr int NB = NT/32;
    constexpr int NW = NT/2;
    constexpr int NT8 = NW/8;
    constexpr int NT16 = NW/16;

    extern __shared__ char smraw[];
    char* sm = (char*)(((uintptr_t)smraw + 1023) & ~(uintptr_t)1023);
    uint32_t sm32 = smem_u32(sm);

    int tid = threadIdx.x;
    int wid = tid >> 5, lane = tid & 31;
    int z = blockIdx.z;
    int proj = 0, hsel = 0;
    if (MODE == 3) {
        proj = z / HH; hsel = z % HH;
        const __half* w = (proj == 0) ? qkv.w0 : (proj == 1) ? qkv.w1 : qkv.w2;
        Bh = w + (size_t)hsel*CC*DD;
    } else {
        Ah += (size_t)z * strideA;
        Bh += (size_t)z * strideB;
        if (MODE == 2) C += (size_t)z * strideC;
    }
    int bm = blockIdx.y * 128, bn = blockIdx.x * NT;

    int wm = (wid & 3) * 32;
    int wn = (wid >> 2) * NW;

    int lr = lane & 7;
    int a_r = lr + ((lane & 8) ? 8 : 0);
    int a_k = (lane & 16) ? 16 : 0;
    int b_r = lr + ((lane & 16) ? 8 : 0);
    int b_k = (lane & 8) ? 16 : 0;

    int g_row = tid >> 3, g_ch = tid & 7;

    float acc[2][NT8][4];
    #pragma unroll
    for (int mt = 0; mt < 2; mt++)
        #pragma unroll
        for (int nt = 0; nt < NT8; nt++)
            #pragma unroll
            for (int j = 0; j < 4; j++) acc[mt][nt][j] = 0.f;

    int nk = Ktot >> 6;

    auto load_stage = [&](int t) {
        int stg = (t & 1) * STAGE;
        int k0 = t << 6;
        #pragma unroll
        for (int i = 0; i < 4; i++) {
            int row = g_row + i*32;
            uint32_t so = sm32 + stg + SWZ(row*128 + g_ch*16);
            CP16(so + SA_H, Ah + (size_t)(bm+row)*lda + k0 + g_ch*8);
        }
        #pragma unroll
        for (int i = 0; i < NB; i++) {
            int row = g_row + i*32;
            uint32_t so = sm32 + stg + SWZ(row*128 + g_ch*16);
            CP16(so + SB_H, Bh + (size_t)(bn+row)*lda + k0 + g_ch*8);
        }
        CP_COMMIT();
    };

    load_stage(0);
    if (nk > 1) load_stage(1);

    for (int t = 0; t < nk; t++) {
        if (t < nk - 1) { CP_WAIT(1); } else { CP_WAIT(0); }
        __syncthreads();
        int stg = (t & 1) * STAGE;
        uint32_t baseA_h = sm32 + stg + SA_H;
        uint32_t baseB_h = sm32 + stg + SB_H;

        #pragma unroll
        for (int kt = 0; kt < 4; kt++) {
            int kb = kt*32;
            uint32_t ah[2][4];
            #pragma unroll
            for (int mt = 0; mt < 2; mt++) {
                uint32_t off = SWZ((wm + mt*16 + a_r)*128 + kb + a_k);
                LDSM_X4(ah[mt][0], ah[mt][1], ah[mt][2], ah[mt][3], baseA_h + off);
            }
            uint32_t bh[NT16][4];
            #pragma unroll
            for (int n2 = 0; n2 < NT16; n2++) {
                uint32_t off = SWZ((wn + n2*16 + b_r)*128 + kb + b_k);
                LDSM_X4(bh[n2][0], bh[n2][1], bh[n2][2], bh[n2][3], baseB_h + off);
            }
            #pragma unroll
            for (int mt = 0; mt < 2; mt++) {
                #pragma unroll
                for (int n2 = 0; n2 < NT16; n2++) {
                    MMA_F16(acc[mt][n2*2],   ah[mt], bh[n2][0], bh[n2][1]);
                    MMA_F16(acc[mt][n2*2+1], ah[mt], bh[n2][2], bh[n2][3]);
                }
            }
        }
        __syncthreads();
        if (t + 2 < nk) load_stage(t + 2);
    }

    // ---- epilogue ----
    int mrow0 = bm + wm + (lane >> 2);
    int ncol0 = bn + wn + (lane & 3) * 2;
    #pragma unroll
    for (int mt = 0; mt < 2; mt++) {
        #pragma unroll
        for (int half = 0; half < 2; half++) {
            int m = mrow0 + mt*16 + half*8;
            #pragma unroll
            for (int nt = 0; nt < NT8; nt++) {
                int n = ncol0 + nt*8;
                float v0 = acc[mt][nt][half*2];
                float v1 = acc[mt][nt][half*2+1];
                if (MODE == 1) {
                    v0 = fmaxf(v0 + bias[n],   0.f);
                    v1 = fmaxf(v1 + bias[n+1], 0.f);
                    __half2 hh2;
                    hh2.x = __float2half(v0); hh2.y = __float2half(v1);
                    *(__half2*)(Oh + (size_t)m*ldo + n) = hh2;
                } else if (MODE == 2) {
                    float2 rr = *(const float2*)(res + (size_t)m*ldc + n);
                    float2 o;
                    o.x = v0 + bias[n]   + rr.x;
                    o.y = v1 + bias[n+1] + rr.y;
                    *(float2*)(C + (size_t)m*ldc + n) = o;
                } else if (MODE == 3) {
                    if (proj == 0) { v0 *= SCALE_L2E; v1 *= SCALE_L2E; }
                    __half2 hh2;
                    hh2.x = __float2half(v0); hh2.y = __float2half(v1);
                    __half* p = (proj == 0) ? qkv.qh : (proj == 1) ? qkv.kh : qkv.vh;
                    size_t o = (((size_t)(m >> 11)*HH + hsel)*TT + (m & (TT-1)))*DD + n;
                    *(__half2*)(p + o) = hh2;
                }
            }
        }
    }
}

// ===================== HMMA flash attention (causal, paired tiles) =========
// 128 threads (4 warps), warp owns 16 q rows. fp16 1-term; Q pre-scaled.
// LOAD BALANCE: grid.x = 16; CTA bx processes q-tile (31-bx) then (bx):
// total work per CTA = 33 k-tiles, constant -> one balanced wave (384 CTAs).
__global__ __launch_bounds__(128) void attn_kernel(
    const __half* __restrict__ Qh, const __half* __restrict__ Kh,
    const __half* __restrict__ Vh, __half* __restrict__ O)
{
    extern __shared__ char smraw[];
    char* sm = (char*)(((uintptr_t)smraw + 1023) & ~(uintptr_t)1023);
    uint32_t sm32 = smem_u32(sm);

    constexpr int QH_O = 0, STG_O = 8192, STG_SZ = 16384;
    constexpr int NQT = TT/64;                   // 32 q tiles
    constexpr uint32_t ONE2 = 0x3C003C00u;       // half2(1.0, 1.0)

    int bx = blockIdx.x;                         // 0..15
    int bh = blockIdx.y;
    int b = bh / HH, h = bh % HH;
    int tid = threadIdx.x, wid = tid >> 5, lane = tid & 31;
    size_t base = (size_t)bh * TT * DD;

    int lr = lane & 7;
    int a_r = lr + ((lane & 8) ? 8 : 0);
    int a_k = (lane & 16) ? 16 : 0;
    int b_r = lr + ((lane & 16) ? 8 : 0);
    int b_k = (lane & 8) ? 16 : 0;
    int v_r = lr + ((lane & 8) ? 8 : 0);
    int v_k = (lane & 16) ? 16 : 0;
    int wm = wid * 16;

    #pragma unroll 1
    for (int pass = 0; pass < 2; pass++) {
        int qt = pass ? bx : (NQT - 1 - bx);     // long tile first

        __syncthreads();   // Q smem region free before overwrite

        // ---- Q tile: 64 rows x 128B = 512 chunks = 128 thr x 4 iters ----
        #pragma unroll
        for (int i = 0; i < 4; i++) {
            int idx = tid + i*128; int row = idx >> 3, ch = idx & 7;
            uint32_t so = sm32 + SWZ(row*128 + ch*16);
            size_t ga = base + (size_t)(qt*64 + row)*DD + ch*8;
            CP16(so + QH_O, Qh + ga);
        }
        auto load_kv = [&](int kt) {
            int stg = STG_O + (kt & 1) * STG_SZ;
            #pragma unroll
            for (int i = 0; i < 4; i++) {
                int idx = tid + i*128; int row = idx >> 3, ch = idx & 7;
                uint32_t so = sm32 + stg + SWZ(row*128 + ch*16);
                size_t ga = base + (size_t)(kt*64 + row)*DD + ch*8;
                CP16(so,        Kh + ga);
                CP16(so + 8192, Vh + ga);
            }
            CP_COMMIT();
        };
        load_kv(0);
        if (qt >= 1) load_kv(1);

        float o[8][4];
        #pragma unroll
        for (int nf = 0; nf < 8; nf++)
            #pragma unroll
            for (int j = 0; j < 4; j++) o[nf][j] = 0.f;
        float osum[4] = {0.f, 0.f, 0.f, 0.f};
        float mrow0 = -1e30f, mrow1 = -1e30f;

        if (qt >= 1) { CP_WAIT(1); } else { CP_WAIT(0); }
        __syncthreads();

        uint32_t qhf[4][4];
        #pragma unroll
        for (int kc = 0; kc < 4; kc++) {
            uint32_t off = SWZ((wm + a_r)*128 + kc*32 + a_k);
            LDSM_X4(qhf[kc][0], qhf[kc][1], qhf[kc][2], qhf[kc][3], sm32 + QH_O + off);
        }

        for (int kt = 0; kt <= qt; kt++) {
            if (kt > 0) {
                if (kt < qt) { CP_WAIT(1); } else { CP_WAIT(0); }
                __syncthreads();
            }
            uint32_t kbh = sm32 + STG_O + (kt & 1)*STG_SZ;
            uint32_t vbh = kbh + 8192;

            // ---- S = Q K^T (log2 domain; Q pre-scaled) ----
            float s[8][4];
            #pragma unroll
            for (int nf = 0; nf < 8; nf++)
                #pragma unroll
                for (int j = 0; j < 4; j++) s[nf][j] = 0.f;

            #pragma unroll
            for (int kc = 0; kc < 4; kc++) {
                #pragma unroll
                for (int c2 = 0; c2 < 4; c2++) {
                    uint32_t h4[4];
                    uint32_t off = SWZ((c2*16 + b_r)*128 + kc*32 + b_k);
                    LDSM_X4(h4[0], h4[1], h4[2], h4[3], kbh + off);
                    MMA_F16(s[c2*2],   qhf[kc], h4[0], h4[1]);
                    MMA_F16(s[c2*2+1], qhf[kc], h4[2], h4[3]);
                }
            }

            // ---- causal mask on diagonal tile ----
            if (kt == qt) {
                int r0 = wm + (lane >> 2), r1 = r0 + 8;
                #pragma unroll
                for (int nf = 0; nf < 8; nf++) {
                    int c = nf*8 + (lane & 3)*2;
                    if (c   > r0) s[nf][0] = -1e30f;
                    if (c+1 > r0) s[nf][1] = -1e30f;
                    if (c   > r1) s[nf][2] = -1e30f;
                    if (c+1 > r1) s[nf][3] = -1e30f;
                }
            }

            // ---- online softmax: max, then f16x2 exp2 ----
            float t0 = -1e30f, t1 = -1e30f;
            #pragma unroll
            for (int nf = 0; nf < 8; nf++) {
                t0 = fmaxf(t0, fmaxf(s[nf][0], s[nf][1]));
                t1 = fmaxf(t1, fmaxf(s[nf][2], s[nf][3]));
            }
            t0 = fmaxf(t0, __shfl_xor_sync(0xffffffffu, t0, 1));
            t0 = fmaxf(t0, __shfl_xor_sync(0xffffffffu, t0, 2));
            t1 = fmaxf(t1, __shfl_xor_sync(0xffffffffu, t1, 1));
            t1 = fmaxf(t1, __shfl_xor_sync(0xffffffffu, t1, 2));
            float mn0 = fmaxf(mrow0, t0), mn1 = fmaxf(mrow1, t1);
            float al0 = fexp2(mrow0 - mn0), al1 = fexp2(mrow1 - mn1);
            mrow0 = mn0; mrow1 = mn1;

            uint32_t p2[8][2];
            #pragma unroll
            for (int nf = 0; nf < 8; nf++) {
                p2[nf][0] = hexp2_2(pack_h2(s[nf][0] - mn0, s[nf][1] - mn0));
                p2[nf][1] = hexp2_2(pack_h2(s[nf][2] - mn1, s[nf][3] - mn1));
            }

            // ---- rescale accumulators ----
            #pragma unroll
            for (int nf = 0; nf < 8; nf++) {
                o[nf][0] *= al0; o[nf][1] *= al0;
                o[nf][2] *= al1; o[nf][3] *= al1;
            }
            osum[0] *= al0; osum[1] *= al0; osum[2] *= al1; osum[3] *= al1;

            // ---- O += P V and row-sum MMA ----
            #pragma unroll
            for (int sk = 0; sk < 4; sk++) {
                uint32_t pha[4];
                pha[0] = p2[sk*2][0];   pha[1] = p2[sk*2][1];
                pha[2] = p2[sk*2+1][0]; pha[3] = p2[sk*2+1][1];
                MMA_F16(osum, pha, ONE2, ONE2);
                #pragma unroll
                for (int c2 = 0; c2 < 4; c2++) {
                    uint32_t vh4[4];
                    uint32_t off = SWZ((sk*16 + v_r)*128 + c2*32 + v_k);
                    LDSM_X4T(vh4[0], vh4[1], vh4[2], vh4[3], vbh + off);
                    MMA_F16(o[c2*2],   pha, vh4[0], vh4[1]);
                    MMA_F16(o[c2*2+1], pha, vh4[2], vh4[3]);
                }
            }

            __syncthreads();
            if (kt + 2 <= qt) load_kv(kt + 2);
        }

        // ---- epilogue: O / rowsum, write fp16 [B,T,C] ----
        float inv0 = 1.0f / osum[0], inv1 = 1.0f / osum[2];
        int r0 = qt*64 + wm + (lane >> 2), r1 = r0 + 8;
        size_t ob = (size_t)b * TT;
        #pragma unroll
        for (int nf = 0; nf < 8; nf++) {
            int d = nf*8 + (lane & 3)*2;
            __half2 w0, w1;
            w0.x = __float2half(o[nf][0]*inv0); w0.y = __float2half(o[nf][1]*inv0);
            w1.x = __float2half(o[nf][2]*inv1); w1.y = __float2half(o[nf][3]*inv1);
            *(__half2*)(O + (ob + r0)*CC + h*DD + d) = w0;
            *(__half2*)(O + (ob + r1)*CC + h*DD + d) = w1;
        }
    }
}

#define ATTN_SMEM (1024 + 8192 + 2*16384)
#define MM_SMEM(NT) (1024 + 2*(16384 + (NT)*128))

// ===================== launch ===============================================
extern "C" void kernel_launch(void* const* d_in, const int* in_sizes, int n_in,
                              void* d_out, int out_size)
{
    const float* x    = (const float*)d_in[0];
    const float* ln1g = (const float*)d_in[1];
    const float* ln1b = (const float*)d_in[2];
    const float* wq   = (const float*)d_in[3];
    const float* wk   = (const float*)d_in[4];
    const float* wv   = (const float*)d_in[5];
    const float* ln2g = (const float*)d_in[6];
    const float* ln2b = (const float*)d_in[7];
    const float* wh   = (const float*)d_in[8];
    const float* bh   = (const float*)d_in[9];
    const float* wp   = (const float*)d_in[10];
    const float* bp   = (const float*)d_in[11];
    float* out = (float*)d_out;

    float *x1;
    __half *atth, *hh, *h2h, *hidh;
    __half *qh, *kh, *vh;
    __half *wqh, *wkh, *wvh, *whh, *wph;
    cudaGetSymbolAddress((void**)&atth, g_atth);
    cudaGetSymbolAddress((void**)&x1,   g_x1);
    cudaGetSymbolAddress((void**)&hh,   g_hh);
    cudaGetSymbolAddress((void**)&h2h,  g_h2h);
    cudaGetSymbolAddress((void**)&hidh, g_hidh);
    cudaGetSymbolAddress((void**)&qh,   g_qh);
    cudaGetSymbolAddress((void**)&kh,   g_kh);
    cudaGetSymbolAddress((void**)&vh,   g_vh);
    cudaGetSymbolAddress((void**)&wqh,  g_wqh);
    cudaGetSymbolAddress((void**)&wkh,  g_wkh);
    cudaGetSymbolAddress((void**)&wvh,  g_wvh);
    cudaGetSymbolAddress((void**)&whh,  g_whh);
    cudaGetSymbolAddress((void**)&wph,  g_wph);

    cudaFuncSetAttribute(attn_kernel,
        cudaFuncAttributeMaxDynamicSharedMemorySize, ATTN_SMEM);
    cudaFuncSetAttribute(mm_kernel<64,3>,
        cudaFuncAttributeMaxDynamicSharedMemorySize, MM_SMEM(64));
    cudaFuncSetAttribute(mm_kernel<128,1>,
        cudaFuncAttributeMaxDynamicSharedMemorySize, MM_SMEM(128));
    cudaFuncSetAttribute(mm_kernel<64,2>,
        cudaFuncAttributeMaxDynamicSharedMemorySize, MM_SMEM(64));

    // weight prep: ALL weights in ONE launch (transpose + fp16 round)
    wprep_kernel<<<6336, 256>>>(wq, wk, wv, wh, wp, wqh, wkh, wvh, whh, wph);

    // LN1 -> fp16
    ln_kernel<false><<<BT, 256>>>(x, nullptr, ln1g, ln1b, hh, nullptr);

    // QKV projection (z = proj*HH + h, NT=64 tiles)
    QKVOut qkv;
    qkv.w0 = wqh; qkv.w1 = wkh; qkv.w2 = wvh;
    qkv.qh = qh; qkv.kh = kh; qkv.vh = vh;
    QKVOut qkv0 = {};
    mm_kernel<64,3><<<dim3(1, BT/128, 3*HH), 256, MM_SMEM(64)>>>(
        hh, CC, 0, nullptr, 0,
        nullptr, 0, 0, CC, nullptr, nullptr, nullptr, 0, qkv);

    // HMMA flash attention (paired q tiles: grid.x=16, constant 33 units/CTA)
    attn_kernel<<<dim3(TT/128, BB*HH), 128, ATTN_SMEM>>>(qh, kh, vh, atth);

    // residual (fp16 att) + LN2 -> fp16 (+x1 f32)
    ln_kernel<true><<<BT, 256>>>(x, atth, ln2g, ln2b, h2h, x1);

    // MLP (HMMA); MLP1 NT=128, MLP2 NT=64 (proven)
    mm_kernel<128,1><<<dim3(C4/128, BT/128, 1), 256, MM_SMEM(128)>>>(
        h2h, CC, 0, whh, 0, nullptr, 0, 0, CC, bh, nullptr,
        hidh, C4, qkv0);
    mm_kernel<64,2><<<dim3(CC/64, BT/128, 1), 256, MM_SMEM(64)>>>(
        hidh, C4, 0, wph, 0, out, CC, 0, C4, bp, x1,
        nullptr, 0, qkv0);
}

// round 17
// speedup vs baseline: 1.0424x; 1.0007x over previous
#include <cuda_runtime.h>
#include <cuda_fp16.h>
#include <cstdint>

#define BB 2
#define TT 2048
#define CC 768
#define HH 12
#define DD 64
#define BT (BB*TT)          // 4096 rows
#define C4 (4*CC)           // 3072
#define SCALE_L2E (0.03608439182435161f * 1.4426950408889634f)  // 1/sqrt(C)*log2(e)

// ===================== PTX helpers (sm_80-compatible only) ==================
__device__ __forceinline__ uint32_t smem_u32(const void* p) {
    uint32_t a;
    asm("{ .reg .u64 t; cvta.to.shared.u64 t, %1; cvt.u32.u64 %0, t; }"
        : "=r"(a) : "l"(p));
    return a;
}

#define CP16(s, g) \
    asm volatile("cp.async.cg.shared.global [%0], [%1], 16;" :: "r"(s), "l"(g))
#define CP_COMMIT() asm volatile("cp.async.commit_group;" ::: "memory")
#define CP_WAIT(n)  asm volatile("cp.async.wait_group %0;" :: "n"(n) : "memory")

#define LDSM_X4(r0, r1, r2, r3, a) \
    asm volatile("ldmatrix.sync.aligned.m8n8.x4.shared.b16 {%0,%1,%2,%3}, [%4];" \
        : "=r"(r0), "=r"(r1), "=r"(r2), "=r"(r3) : "r"(a))

#define LDSM_X4T(r0, r1, r2, r3, a) \
    asm volatile("ldmatrix.sync.aligned.m8n8.x4.trans.shared.b16 {%0,%1,%2,%3}, [%4];" \
        : "=r"(r0), "=r"(r1), "=r"(r2), "=r"(r3) : "r"(a))

#define MMA_F16(d, a, b0, b1) \
    asm volatile("mma.sync.aligned.m16n8k16.row.col.f32.f16.f16.f32 " \
        "{%0,%1,%2,%3}, {%4,%5,%6,%7}, {%8,%9}, {%0,%1,%2,%3};" \
        : "+f"((d)[0]), "+f"((d)[1]), "+f"((d)[2]), "+f"((d)[3]) \
        : "r"((a)[0]), "r"((a)[1]), "r"((a)[2]), "r"((a)[3]), "r"(b0), "r"(b1))

#define SWZ(x) ((x) ^ (((x) >> 3) & 0x70))

__device__ __forceinline__ uint32_t pack_h2(float lo, float hi) {
    uint32_t r;
    asm("cvt.rn.f16x2.f32 %0, %1, %2;" : "=r"(r) : "f"(hi), "f"(lo));
    return r;
}
__device__ __forceinline__ uint32_t hexp2_2(uint32_t a) {
    uint32_t r;
    asm("ex2.approx.f16x2 %0, %1;" : "=r"(r) : "r"(a));
    return r;
}
__device__ __forceinline__ float fexp2(float x) {
    float r;
    asm("ex2.approx.ftz.f32 %0, %1;" : "=f"(r) : "f"(x));
    return r;
}

// ===================== scratch (static device memory) ======================
__device__ __half g_atth[BT*CC];            // attention out, fp16
__device__ float g_x1 [BT*CC];
__device__ __half g_hh [BT*CC];
__device__ __half g_h2h[BT*CC];
__device__ __half g_hidh[(size_t)BT*C4];
// qkv, layout [B,H,T,D], fp16; Q pre-scaled by SCALE_L2E (log2 domain)
__device__ __half g_qh[BT*CC];
__device__ __half g_kh[BT*CC];
__device__ __half g_vh[BT*CC];
__device__ __half g_wqh[HH*DD*CC];
__device__ __half g_wkh[HH*DD*CC];
__device__ __half g_wvh[HH*DD*CC];
__device__ __half g_whh[(size_t)C4*CC];
__device__ __half g_wph[(size_t)CC*C4];

struct QKVOut {
    const __half *w0, *w1, *w2;
    __half *qh, *kh, *vh;
};

// ===================== fused weight prep (ALL weights, ONE launch) =========
__global__ __launch_bounds__(256) void wprep_kernel(
    const float* __restrict__ wq, const float* __restrict__ wk,
    const float* __restrict__ wv, const float* __restrict__ wh,
    const float* __restrict__ wp,
    __half* __restrict__ wqh, __half* __restrict__ wkh,
    __half* __restrict__ wvh, __half* __restrict__ whh,
    __half* __restrict__ wph)
{
    int id = blockIdx.x;
    const float* in; __half* oh;
    int R, Cn, x, y; long zo = 0;
    if (id < 1728) {                 // wq/wk/wv: 3 sections x 12 heads x (2x24)
        int sec = id / 576, r = id % 576;
        int z = r / 48, rr = r % 48;
        x = rr & 1; y = rr >> 1;
        R = CC; Cn = DD;
        zo = (long)z * CC * DD;
        in = (sec == 0) ? wq : (sec == 1) ? wk : wv;
        oh = (sec == 0) ? wqh : (sec == 1) ? wkh : wvh;
    } else if (id < 4032) {          // wh: 96 x-tiles, 24 y-tiles
        int r = id - 1728;
        x = r % 96; y = r / 96;
        R = CC; Cn = C4; in = wh; oh = whh;
    } else {                         // wp: 24 x-tiles, 96 y-tiles
        int r = id - 4032;
        x = r % 24; y = r / 24;
        R = C4; Cn = CC; in = wp; oh = wph;
    }

    __shared__ float ts[32][33];
    int r0 = y * 32, c0 = x * 32;
    int tx = threadIdx.x & 31, ty = threadIdx.x >> 5;
    #pragma unroll
    for (int i = 0; i < 4; i++) {
        int r = r0 + ty + i*8;
        ts[ty + i*8][tx] = in[zo + (size_t)r*Cn + c0 + tx];
    }
    __syncthreads();
    #pragma unroll
    for (int i = 0; i < 4; i++) {
        int cc = ty + i*8;
        size_t oi = zo + (size_t)(c0 + cc)*R + r0 + tx;
        oh[oi] = __float2half(ts[tx][cc]);
    }
}

// ===================== LayerNorm -> fp16 (+opt fp16 residual) ==============
template<bool ADD>
__global__ __launch_bounds__(256) void ln_kernel(
    const float* __restrict__ x, const __half* __restrict__ addh,
    const float* __restrict__ g, const float* __restrict__ be,
    __half* __restrict__ oh, float* __restrict__ outsum)
{
    int row = blockIdx.x;
    int tid = threadIdx.x;
    const float* xr = x + (size_t)row*CC;
    const __half* ar = addh + (size_t)row*CC;
    float v[3]; float s = 0.f, sq = 0.f;
    #pragma unroll
    for (int i = 0; i < 3; i++) {
        int c = tid + i*256;
        float val = xr[c];
        if (ADD) val += __half2float(ar[c]);
        v[i] = val; s += val; sq = fmaf(val, val, sq);
    }
    #pragma unroll
    for (int o = 16; o > 0; o >>= 1) {
        s  += __shfl_down_sync(0xffffffffu, s,  o);
        sq += __shfl_down_sync(0xffffffffu, sq, o);
    }
    __shared__ float rs[8], rq[8], stat[2];
    if ((tid & 31) == 0) { rs[tid>>5] = s; rq[tid>>5] = sq; }
    __syncthreads();
    if (tid == 0) {
        float ts = 0.f, tq = 0.f;
        #pragma unroll
        for (int i = 0; i < 8; i++) { ts += rs[i]; tq += rq[i]; }
        float mu  = ts * (1.0f/CC);
        float var = tq * (1.0f/CC) - mu*mu;
        stat[0] = mu; stat[1] = rsqrtf(var + 1e-5f);
    }
    __syncthreads();
    float mu = stat[0], rstd = stat[1];
    #pragma unroll
    for (int i = 0; i < 3; i++) {
        int c = tid + i*256;
        float val = (v[i]-mu)*rstd*g[c] + be[c];
        oh[(size_t)row*CC + c] = __float2half(val);
        if (ADD) outsum[(size_t)row*CC + c] = v[i];
    }
}

// ===================== HMMA (mma.sync) GEMM =================================
// C[M,N] = A[M,K] * B[N,K]^T, fp16 1-term.
// MODE 1: +bias, ReLU, store fp16.  MODE 2: +bias +residual, f32 store.
// MODE 3: fused QKV (z = proj*HH + h), out fp16 [B,H,T,D], Q pre-scaled.
template<int NT, int MODE>
__global__ __launch_bounds__(256)
void mm_kernel(
    const __half* __restrict__ Ah, int lda, long strideA,
    const __half* __restrict__ Bh, long strideB,
    float* __restrict__ C, int ldc, long strideC,
    int Ktot,
    const float* __restrict__ bias, const float* __restrict__ res,
    __half* __restrict__ Oh, int ldo,
    QKVOut qkv)
{
    static_assert(NT == 64 || NT == 128, "NT");
    constexpr int SA_H = 0;
    constexpr int SB_H = 16384;
    constexpr int STAGE = 16384 + NT*128;
    constexpr int NB = NT/32;
    constexpr int NW = NT/2;
    constexpr int NT8 = NW/8;
    constexpr int NT16 = NW/16;

    extern __shared__ char smraw[];
    char* sm = (char*)(((uintptr_t)smraw + 1023) & ~(uintptr_t)1023);
    uint32_t sm32 = smem_u32(sm);

    int tid = threadIdx.x;
    int wid = tid >> 5, lane = tid & 31;
    int z = blockIdx.z;
    int proj = 0, hsel = 0;
    if (MODE == 3) {
        proj = z / HH; hsel = z % HH;
        const __half* w = (proj == 0) ? qkv.w0 : (proj == 1) ? qkv.w1 : qkv.w2;
        Bh = w + (size_t)hsel*CC*DD;
    } else {
        Ah += (size_t)z * strideA;
        Bh += (size_t)z * strideB;
        if (MODE == 2) C += (size_t)z * strideC;
    }
    int bm = blockIdx.y * 128, bn = blockIdx.x * NT;

    int wm = (wid & 3) * 32;
    int wn = (wid >> 2) * NW;

    int lr = lane & 7;
    int a_r = lr + ((lane & 8) ? 8 : 0);
    int a_k = (lane & 16) ? 16 : 0;
    int b_r = lr + ((lane & 16) ? 8 : 0);
    int b_k = (lane & 8) ? 16 : 0;

    int g_row = tid >> 3, g_ch = tid & 7;

    float acc[2][NT8][4];
    #pragma unroll
    for (int mt = 0; mt < 2; mt++)
        #pragma unroll
        for (int nt = 0; nt < NT8; nt++)
            #pragma unroll
            for (int j = 0; j < 4; j++) acc[mt][nt][j] = 0.f;

    int nk = Ktot >> 6;

    auto load_stage = [&](int t) {
        int stg = (t & 1) * STAGE;
        int k0 = t << 6;
        #pragma unroll
        for (int i = 0; i < 4; i++) {
            int row = g_row + i*32;
            uint32_t so = sm32 + stg + SWZ(row*128 + g_ch*16);
            CP16(so + SA_H, Ah + (size_t)(bm+row)*lda + k0 + g_ch*8);
        }
        #pragma unroll
        for (int i = 0; i < NB; i++) {
            int row = g_row + i*32;
            uint32_t so = sm32 + stg + SWZ(row*128 + g_ch*16);
            CP16(so + SB_H, Bh + (size_t)(bn+row)*lda + k0 + g_ch*8);
        }
        CP_COMMIT();
    };

    load_stage(0);
    if (nk > 1) load_stage(1);

    for (int t = 0; t < nk; t++) {
        if (t < nk - 1) { CP_WAIT(1); } else { CP_WAIT(0); }
        __syncthreads();
        int stg = (t & 1) * STAGE;
        uint32_t baseA_h = sm32 + stg + SA_H;
        uint32_t baseB_h = sm32 + stg + SB_H;

        #pragma unroll
        for (int kt = 0; kt < 4; kt++) {
            int kb = kt*32;
            uint32_t ah[2][4];
            #pragma unroll
            for (int mt = 0; mt < 2; mt++) {
                uint32_t off = SWZ((wm + mt*16 + a_r)*128 + kb + a_k);
                LDSM_X4(ah[mt][0], ah[mt][1], ah[mt][2], ah[mt][3], baseA_h + off);
            }
            uint32_t bh[NT16][4];
            #pragma unroll
            for (int n2 = 0; n2 < NT16; n2++) {
                uint32_t off = SWZ((wn + n2*16 + b_r)*128 + kb + b_k);
                LDSM_X4(bh[n2][0], bh[n2][1], bh[n2][2], bh[n2][3], baseB_h + off);
            }
            #pragma unroll
            for (int mt = 0; mt < 2; mt++) {
                #pragma unroll
                for (int n2 = 0; n2 < NT16; n2++) {
                    MMA_F16(acc[mt][n2*2],   ah[mt], bh[n2][0], bh[n2][1]);
                    MMA_F16(acc[mt][n2*2+1], ah[mt], bh[n2][2], bh[n2][3]);
                }
            }
        }
        __syncthreads();
        if (t + 2 < nk) load_stage(t + 2);
    }

    // ---- epilogue ----
    int mrow0 = bm + wm + (lane >> 2);
    int ncol0 = bn + wn + (lane & 3) * 2;
    #pragma unroll
    for (int mt = 0; mt < 2; mt++) {
        #pragma unroll
        for (int half = 0; half < 2; half++) {
            int m = mrow0 + mt*16 + half*8;
            #pragma unroll
            for (int nt = 0; nt < NT8; nt++) {
                int n = ncol0 + nt*8;
                float v0 = acc[mt][nt][half*2];
                float v1 = acc[mt][nt][half*2+1];
                if (MODE == 1) {
                    v0 = fmaxf(v0 + bias[n],   0.f);
                    v1 = fmaxf(v1 + bias[n+1], 0.f);
                    __half2 hh2;
                    hh2.x = __float2half(v0); hh2.y = __float2half(v1);
                    *(__half2*)(Oh + (size_t)m*ldo + n) = hh2;
                } else if (MODE == 2) {
                    float2 rr = *(const float2*)(res + (size_t)m*ldc + n);
                    float2 o;
                    o.x = v0 + bias[n]   + rr.x;
                    o.y = v1 + bias[n+1] + rr.y;
                    *(float2*)(C + (size_t)m*ldc + n) = o;
                } else if (MODE == 3) {
                    if (proj == 0) { v0 *= SCALE_L2E; v1 *= SCALE_L2E; }
                    __half2 hh2;
                    hh2.x = __float2half(v0); hh2.y = __float2half(v1);
                    __half* p = (proj == 0) ? qkv.qh : (proj == 1) ? qkv.kh : qkv.vh;
                    size_t o = (((size_t)(m >> 11)*HH + hsel)*TT + (m & (TT-1)))*DD + n;
                    *(__half2*)(p + o) = hh2;
                }
            }
        }
    }
}

// ===================== HMMA flash attention (causal, paired tiles) =========
// 128 threads (4 warps), warp owns 16 q rows. fp16 1-term; Q pre-scaled.
// LOAD BALANCE: grid.x = 16; CTA bx processes q-tile (31-bx) then (bx).
// ILP: exp generation fused into the PV loop per sk group so MUFU/ALU of
// group sk+1 overlaps tensor-pipe MMAs of group sk (also -12 live regs).
__global__ __launch_bounds__(128) void attn_kernel(
    const __half* __restrict__ Qh, const __half* __restrict__ Kh,
    const __half* __restrict__ Vh, __half* __restrict__ O)
{
    extern __shared__ char smraw[];
    char* sm = (char*)(((uintptr_t)smraw + 1023) & ~(uintptr_t)1023);
    uint32_t sm32 = smem_u32(sm);

    constexpr int QH_O = 0, STG_O = 8192, STG_SZ = 16384;
    constexpr int NQT = TT/64;                   // 32 q tiles
    constexpr uint32_t ONE2 = 0x3C003C00u;       // half2(1.0, 1.0)

    int bx = blockIdx.x;                         // 0..15
    int bh = blockIdx.y;
    int b = bh / HH, h = bh % HH;
    int tid = threadIdx.x, wid = tid >> 5, lane = tid & 31;
    size_t base = (size_t)bh * TT * DD;

    int lr = lane & 7;
    int a_r = lr + ((lane & 8) ? 8 : 0);
    int a_k = (lane & 16) ? 16 : 0;
    int b_r = lr + ((lane & 16) ? 8 : 0);
    int b_k = (lane & 8) ? 16 : 0;
    int v_r = lr + ((lane & 8) ? 8 : 0);
    int v_k = (lane & 16) ? 16 : 0;
    int wm = wid * 16;

    #pragma unroll 1
    for (int pass = 0; pass < 2; pass++) {
        int qt = pass ? bx : (NQT - 1 - bx);     // long tile first

        __syncthreads();   // Q smem region free before overwrite

        // ---- Q tile: 64 rows x 128B = 512 chunks = 128 thr x 4 iters ----
        #pragma unroll
        for (int i = 0; i < 4; i++) {
            int idx = tid + i*128; int row = idx >> 3, ch = idx & 7;
            uint32_t so = sm32 + SWZ(row*128 + ch*16);
            size_t ga = base + (size_t)(qt*64 + row)*DD + ch*8;
            CP16(so + QH_O, Qh + ga);
        }
        auto load_kv = [&](int kt) {
            int stg = STG_O + (kt & 1) * STG_SZ;
            #pragma unroll
            for (int i = 0; i < 4; i++) {
                int idx = tid + i*128; int row = idx >> 3, ch = idx & 7;
                uint32_t so = sm32 + stg + SWZ(row*128 + ch*16);
                size_t ga = base + (size_t)(kt*64 + row)*DD + ch*8;
                CP16(so,        Kh + ga);
                CP16(so + 8192, Vh + ga);
            }
            CP_COMMIT();
        };
        load_kv(0);
        if (qt >= 1) load_kv(1);

        float o[8][4];
        #pragma unroll
        for (int nf = 0; nf < 8; nf++)
            #pragma unroll
            for (int j = 0; j < 4; j++) o[nf][j] = 0.f;
        float osum[4] = {0.f, 0.f, 0.f, 0.f};
        float mrow0 = -1e30f, mrow1 = -1e30f;

        if (qt >= 1) { CP_WAIT(1); } else { CP_WAIT(0); }
        __syncthreads();

        uint32_t qhf[4][4];
        #pragma unroll
        for (int kc = 0; kc < 4; kc++) {
            uint32_t off = SWZ((wm + a_r)*128 + kc*32 + a_k);
            LDSM_X4(qhf[kc][0], qhf[kc][1], qhf[kc][2], qhf[kc][3], sm32 + QH_O + off);
        }

        for (int kt = 0; kt <= qt; kt++) {
            if (kt > 0) {
                if (kt < qt) { CP_WAIT(1); } else { CP_WAIT(0); }
                __syncthreads();
            }
            uint32_t kbh = sm32 + STG_O + (kt & 1)*STG_SZ;
            uint32_t vbh = kbh + 8192;

            // ---- S = Q K^T (log2 domain; Q pre-scaled) ----
            float s[8][4];
            #pragma unroll
            for (int nf = 0; nf < 8; nf++)
                #pragma unroll
                for (int j = 0; j < 4; j++) s[nf][j] = 0.f;

            #pragma unroll
            for (int kc = 0; kc < 4; kc++) {
                #pragma unroll
                for (int c2 = 0; c2 < 4; c2++) {
                    uint32_t h4[4];
                    uint32_t off = SWZ((c2*16 + b_r)*128 + kc*32 + b_k);
                    LDSM_X4(h4[0], h4[1], h4[2], h4[3], kbh + off);
                    MMA_F16(s[c2*2],   qhf[kc], h4[0], h4[1]);
                    MMA_F16(s[c2*2+1], qhf[kc], h4[2], h4[3]);
                }
            }

            // ---- causal mask on diagonal tile ----
            if (kt == qt) {
                int r0 = wm + (lane >> 2), r1 = r0 + 8;
                #pragma unroll
                for (int nf = 0; nf < 8; nf++) {
                    int c = nf*8 + (lane & 3)*2;
                    if (c   > r0) s[nf][0] = -1e30f;
                    if (c+1 > r0) s[nf][1] = -1e30f;
                    if (c   > r1) s[nf][2] = -1e30f;
                    if (c+1 > r1) s[nf][3] = -1e30f;
                }
            }

            // ---- online softmax: max (shfl), then per-group exp+PV ----
            float t0 = -1e30f, t1 = -1e30f;
            #pragma unroll
            for (int nf = 0; nf < 8; nf++) {
                t0 = fmaxf(t0, fmaxf(s[nf][0], s[nf][1]));
                t1 = fmaxf(t1, fmaxf(s[nf][2], s[nf][3]));
            }
            t0 = fmaxf(t0, __shfl_xor_sync(0xffffffffu, t0, 1));
            t0 = fmaxf(t0, __shfl_xor_sync(0xffffffffu, t0, 2));
            t1 = fmaxf(t1, __shfl_xor_sync(0xffffffffu, t1, 1));
            t1 = fmaxf(t1, __shfl_xor_sync(0xffffffffu, t1, 2));
            float mn0 = fmaxf(mrow0, t0), mn1 = fmaxf(mrow1, t1);
            float al0 = fexp2(mrow0 - mn0), al1 = fexp2(mrow1 - mn1);
            mrow0 = mn0; mrow1 = mn1;

            // ---- rescale accumulators ----
            #pragma unroll
            for (int nf = 0; nf < 8; nf++) {
                o[nf][0] *= al0; o[nf][1] *= al0;
                o[nf][2] *= al1; o[nf][3] *= al1;
            }
            osum[0] *= al0; osum[1] *= al0; osum[2] *= al1; osum[3] *= al1;

            // ---- per-sk: exp (f16x2) -> row-sum MMA + PV MMAs ----
            #pragma unroll
            for (int sk = 0; sk < 4; sk++) {
                int f0 = sk*2, f1 = sk*2 + 1;
                uint32_t pha[4];
                pha[0] = hexp2_2(pack_h2(s[f0][0] - mn0, s[f0][1] - mn0));
                pha[1] = hexp2_2(pack_h2(s[f0][2] - mn1, s[f0][3] - mn1));
                pha[2] = hexp2_2(pack_h2(s[f1][0] - mn0, s[f1][1] - mn0));
                pha[3] = hexp2_2(pack_h2(s[f1][2] - mn1, s[f1][3] - mn1));
                MMA_F16(osum, pha, ONE2, ONE2);
                #pragma unroll
                for (int c2 = 0; c2 < 4; c2++) {
                    uint32_t vh4[4];
                    uint32_t off = SWZ((sk*16 + v_r)*128 + c2*32 + v_k);
                    LDSM_X4T(vh4[0], vh4[1], vh4[2], vh4[3], vbh + off);
                    MMA_F16(o[c2*2],   pha, vh4[0], vh4[1]);
                    MMA_F16(o[c2*2+1], pha, vh4[2], vh4[3]);
                }
            }

            __syncthreads();
            if (kt + 2 <= qt) load_kv(kt + 2);
        }

        // ---- epilogue: O / rowsum, write fp16 [B,T,C] ----
        float inv0 = 1.0f / osum[0], inv1 = 1.0f / osum[2];
        int r0 = qt*64 + wm + (lane >> 2), r1 = r0 + 8;
        size_t ob = (size_t)b * TT;
        #pragma unroll
        for (int nf = 0; nf < 8; nf++) {
            int d = nf*8 + (lane & 3)*2;
            __half2 w0, w1;
            w0.x = __float2half(o[nf][0]*inv0); w0.y = __float2half(o[nf][1]*inv0);
            w1.x = __float2half(o[nf][2]*inv1); w1.y = __float2half(o[nf][3]*inv1);
            *(__half2*)(O + (ob + r0)*CC + h*DD + d) = w0;
            *(__half2*)(O + (ob + r1)*CC + h*DD + d) = w1;
        }
    }
}

#define ATTN_SMEM (1024 + 8192 + 2*16384)
#define MM_SMEM(NT) (1024 + 2*(16384 + (NT)*128))

// ===================== launch ===============================================
extern "C" void kernel_launch(void* const* d_in, const int* in_sizes, int n_in,
                              void* d_out, int out_size)
{
    const float* x    = (const float*)d_in[0];
    const float* ln1g = (const float*)d_in[1];
    const float* ln1b = (const float*)d_in[2];
    const float* wq   = (const float*)d_in[3];
    const float* wk   = (const float*)d_in[4];
    const float* wv   = (const float*)d_in[5];
    const float* ln2g = (const float*)d_in[6];
    const float* ln2b = (const float*)d_in[7];
    const float* wh   = (const float*)d_in[8];
    const float* bh   = (const float*)d_in[9];
    const float* wp   = (const float*)d_in[10];
    const float* bp   = (const float*)d_in[11];
    float* out = (float*)d_out;

    float *x1;
    __half *atth, *hh, *h2h, *hidh;
    __half *qh, *kh, *vh;
    __half *wqh, *wkh, *wvh, *whh, *wph;
    cudaGetSymbolAddress((void**)&atth, g_atth);
    cudaGetSymbolAddress((void**)&x1,   g_x1);
    cudaGetSymbolAddress((void**)&hh,   g_hh);
    cudaGetSymbolAddress((void**)&h2h,  g_h2h);
    cudaGetSymbolAddress((void**)&hidh, g_hidh);
    cudaGetSymbolAddress((void**)&qh,   g_qh);
    cudaGetSymbolAddress((void**)&kh,   g_kh);
    cudaGetSymbolAddress((void**)&vh,   g_vh);
    cudaGetSymbolAddress((void**)&wqh,  g_wqh);
    cudaGetSymbolAddress((void**)&wkh,  g_wkh);
    cudaGetSymbolAddress((void**)&wvh,  g_wvh);
    cudaGetSymbolAddress((void**)&whh,  g_whh);
    cudaGetSymbolAddress((void**)&wph,  g_wph);

    cudaFuncSetAttribute(attn_kernel,
        cudaFuncAttributeMaxDynamicSharedMemorySize, ATTN_SMEM);
    cudaFuncSetAttribute(mm_kernel<64,3>,
        cudaFuncAttributeMaxDynamicSharedMemorySize, MM_SMEM(64));
    cudaFuncSetAttribute(mm_kernel<128,1>,
        cudaFuncAttributeMaxDynamicSharedMemorySize, MM_SMEM(128));
    cudaFuncSetAttribute(mm_kernel<64,2>,
        cudaFuncAttributeMaxDynamicSharedMemorySize, MM_SMEM(64));

    // weight prep: ALL weights in ONE launch (transpose + fp16 round)
    wprep_kernel<<<6336, 256>>>(wq, wk, wv, wh, wp, wqh, wkh, wvh, whh, wph);

    // LN1 -> fp16
    ln_kernel<false><<<BT, 256>>>(x, nullptr, ln1g, ln1b, hh, nullptr);

    // QKV projection (z = proj*HH + h, NT=64 tiles)
    QKVOut qkv;
    qkv.w0 = wqh; qkv.w1 = wkh; qkv.w2 = wvh;
    qkv.qh = qh; qkv.kh = kh; qkv.vh = vh;
    QKVOut qkv0 = {};
    mm_kernel<64,3><<<dim3(1, BT/128, 3*HH), 256, MM_SMEM(64)>>>(
        hh, CC, 0, nullptr, 0,
        nullptr, 0, 0, CC, nullptr, nullptr, nullptr, 0, qkv);

    // HMMA flash attention (paired q tiles; fused exp->PV groups)
    attn_kernel<<<dim3(TT/128, BB*HH), 128, ATTN_SMEM>>>(qh, kh, vh, atth);

    // residual (fp16 att) + LN2 -> fp16 (+x1 f32)
    ln_kernel<true><<<BT, 256>>>(x, atth, ln2g, ln2b, h2h, x1);

    // MLP (HMMA); MLP1 NT=128, MLP2 NT=64 (proven)
    mm_kernel<128,1><<<dim3(C4/128, BT/128, 1), 256, MM_SMEM(128)>>>(
        h2h, CC, 0, whh, 0, nullptr, 0, 0, CC, bh, nullptr,
        hidh, C4, qkv0);
    mm_kernel<64,2><<<dim3(CC/64, BT/128, 1), 256, MM_SMEM(64)>>>(
        hidh, C4, 0, wph, 0, out, CC, 0, C4, bp, x1,
        nullptr, 0, qkv0);
}